// round 2
// baseline (speedup 1.0000x reference)
#include <cuda_runtime.h>
#include <math.h>

#define NG    1024
#define CG    16
#define HH    64
#define WWD   64
#define HW    4096
#define NELEM (CG*HW)   // 65536 floats per group

// ---------------- scratch (static device globals: no runtime alloc) ----------
__device__ float g_x3[(size_t)NG*CG*HW];          // 256MB conv3x3+silu cache
__device__ float g_rowsum[NG*CG*HH];
__device__ float g_colpart[NG*4*CG*WWD];
__device__ float g_maxpart[NG*4*CG];
__device__ float g_vsumpart[NG*4*CG];
__device__ float g_ah[NG*CG*HH];
__device__ float g_aw[NG*CG*WWD];
__device__ float g_M3[NG*CG];
__device__ float g_v3[NG*CG];
__device__ float g_sc[NG*CG];
__device__ float g_M1[NG*CG];
__device__ float g_v1[NG*CG];
__device__ float g_Z3[NG*CG];
__device__ float g_t1[NG*CG];
__device__ float g_t3[NG*CG];

// ---------------- K1: conv3x3 + silu + row/col sums + x3 strip stats ---------
#define XS_PITCH 68
#define XS_ROWS  18

extern __shared__ float s_xs[];   // 16 * 18 * 68 floats

__global__ __launch_bounds__(256) void k1_conv(
    const float* __restrict__ x, const float* __restrict__ w3,
    const float* __restrict__ b3)
{
    __shared__ float ws[CG*CG*9];   // transposed layout: [(ci*9+k)*16 + co]
    __shared__ float b3s[CG];
    __shared__ float redm[256], redv[256];

    const int n = blockIdx.y, s = blockIdx.x, tid = threadIdx.x;
    const float* xn = x + (size_t)n * NELEM;
    const int r0 = s * 16;

    for (int i = tid; i < CG*CG*9; i += 256) {
        int co = i / 144; int rem = i - co * 144;   // rem = ci*9+k
        ws[rem * 16 + co] = w3[i];
    }
    if (tid < CG) b3s[tid] = b3[tid];

    // stage 18 rows (with zero halo) x 16 channels
    for (int i = tid; i < CG*XS_ROWS*WWD; i += 256) {
        int ci = i / (XS_ROWS*WWD); int rem = i - ci * (XS_ROWS*WWD);
        int rr = rem >> 6; int w = rem & 63;
        int gr = r0 - 1 + rr;
        float v = (gr >= 0 && gr < HH) ? xn[ci*HW + gr*WWD + w] : 0.f;
        s_xs[(ci*XS_ROWS + rr)*XS_PITCH + (w + 1)] = v;
    }
    for (int i = tid; i < CG*XS_ROWS; i += 256) {
        float* row = &s_xs[i * XS_PITCH];
        row[0] = 0.f; row[65] = 0.f; row[66] = 0.f; row[67] = 0.f;
    }
    __syncthreads();

    const int co = tid & 15, r = tid >> 4;   // r: 0..15 local row

    // row sum (channel co, row r0+r)
    {
        const float* row = &s_xs[(co*XS_ROWS + (r + 1))*XS_PITCH + 1];
        float sum = 0.f;
        #pragma unroll
        for (int w = 0; w < WWD; w++) sum += row[w];
        g_rowsum[(n*CG + co)*HH + (r0 + r)] = sum;
    }
    // col partial sums (strip)
    for (int k = 0; k < 4; k++) {
        int idx = tid + k * 256;
        int c = idx >> 6, w = idx & 63;
        float sum = 0.f;
        #pragma unroll
        for (int rr = 1; rr <= 16; rr++)
            sum += s_xs[(c*XS_ROWS + rr)*XS_PITCH + w + 1];
        g_colpart[((n*4 + s)*CG + c)*WWD + w] = sum;
    }

    // conv3x3: thread owns (co, row r)
    float vmax = -1e30f, vsum = 0.f;
    const float bco = b3s[co];
    float* x3out = &g_x3[(size_t)(n*CG + co)*HW + (size_t)(r0 + r)*WWD];

    for (int chunk = 0; chunk < 4; chunk++) {
        const int wb = chunk * 16;
        float acc[16];
        #pragma unroll
        for (int j = 0; j < 16; j++) acc[j] = 0.f;

        for (int ci = 0; ci < CG; ci++) {
            #pragma unroll
            for (int dr = 0; dr < 3; dr++) {
                const float* row = &s_xs[(ci*XS_ROWS + r + dr)*XS_PITCH + wb];
                const int wbase = (ci*9 + dr*3) * 16 + co;
                const float w0 = ws[wbase], w1 = ws[wbase + 16], w2 = ws[wbase + 32];
                float v[18];
                #pragma unroll
                for (int k2 = 0; k2 < 18; k2++) v[k2] = row[k2];
                #pragma unroll
                for (int j = 0; j < 16; j++)
                    acc[j] = fmaf(w0, v[j], fmaf(w1, v[j+1], fmaf(w2, v[j+2], acc[j])));
            }
        }
        #pragma unroll
        for (int j = 0; j < 16; j++) {
            float z = acc[j] + bco;
            float sv = z / (1.f + __expf(-z));   // silu
            x3out[wb + j] = sv;
            vmax = fmaxf(vmax, sv);
            vsum += sv;
        }
    }
    redm[tid] = vmax; redv[tid] = vsum;
    __syncthreads();
    if (tid < CG) {
        float m = -1e30f, vs = 0.f;
        for (int rr = 0; rr < 16; rr++) {
            m = fmaxf(m, redm[rr*16 + tid]);
            vs += redv[rr*16 + tid];
        }
        g_maxpart[(n*4 + s)*CG + tid] = m;
        g_vsumpart[(n*4 + s)*CG + tid] = vs;
    }
}

// ---------------- K2: small matmuls (y, a_h, a_w) + x3 stat finalize ---------
__global__ __launch_bounds__(128) void k2_small(
    const float* __restrict__ w1, const float* __restrict__ b1,
    const float* __restrict__ wh, const float* __restrict__ bh,
    const float* __restrict__ ww, const float* __restrict__ bw)
{
    __shared__ float W1s[256], Whs[256], Wws[256], b1s[16], bhs[16], bws[16];
    const int n = blockIdx.x, tid = threadIdx.x;   // 128 threads

    for (int i = tid; i < 256; i += 128) { W1s[i] = w1[i]; Whs[i] = wh[i]; Wws[i] = ww[i]; }
    if (tid < 16) { b1s[tid] = b1[tid]; bhs[tid] = bh[tid]; bws[tid] = bw[tid]; }
    __syncthreads();

    const int pos = tid;
    float xcol[16];
    if (pos < 64) {
        #pragma unroll
        for (int ci = 0; ci < 16; ci++)
            xcol[ci] = g_rowsum[(n*CG + ci)*HH + pos] * (1.f/64.f);
    } else {
        const int w = pos - 64;
        #pragma unroll
        for (int ci = 0; ci < 16; ci++) {
            float sv = 0.f;
            for (int st = 0; st < 4; st++)
                sv += g_colpart[((n*4 + st)*CG + ci)*WWD + w];
            xcol[ci] = sv * (1.f/64.f);
        }
    }
    float y[16];
    #pragma unroll
    for (int o = 0; o < 16; o++) {
        float t = b1s[o];
        #pragma unroll
        for (int ci = 0; ci < 16; ci++) t = fmaf(W1s[o*16 + ci], xcol[ci], t);
        y[o] = t / (1.f + __expf(-t));   // silu
    }
    if (pos < 64) {
        #pragma unroll
        for (int o = 0; o < 16; o++) {
            float t = bhs[o];
            #pragma unroll
            for (int ci = 0; ci < 16; ci++) t = fmaf(Whs[o*16 + ci], y[ci], t);
            g_ah[(n*CG + o)*HH + pos] = 1.f / (1.f + __expf(-t));
        }
    } else {
        const int w = pos - 64;
        #pragma unroll
        for (int o = 0; o < 16; o++) {
            float t = bws[o];
            #pragma unroll
            for (int ci = 0; ci < 16; ci++) t = fmaf(Wws[o*16 + ci], y[ci], t);
            g_aw[(n*CG + o)*WWD + w] = 1.f / (1.f + __expf(-t));
        }
    }
    if (tid < 16) {
        float m = -1e30f, vs = 0.f;
        for (int st = 0; st < 4; st++) {
            m = fmaxf(m, g_maxpart[(n*4 + st)*CG + tid]);
            vs += g_vsumpart[(n*4 + st)*CG + tid];
        }
        g_M3[n*CG + tid] = m;
        g_v3[n*CG + tid] = vs * (1.f/4096.f);
    }
}

// ---------------- K3: x1 stats (sum, sumsq, max, min) + Z3 -------------------
__global__ __launch_bounds__(512) void k3_stats(
    const float* __restrict__ x, const float* __restrict__ gamma,
    const float* __restrict__ beta)
{
    __shared__ float ahs[CG*HH];
    __shared__ float r_s[16], r_sq[16], r_mx[16], r_mn[16], r_z3[16];
    const int n = blockIdx.x, tid = threadIdx.x;   // 512 = 16 warps

    for (int i = tid; i < CG*HH; i += 512) ahs[i] = g_ah[n*CG*HH + i];
    __syncthreads();

    const int c = tid >> 5, l = tid & 31;
    const float aw0 = g_aw[(n*CG + c)*WWD + l];
    const float aw1 = g_aw[(n*CG + c)*WWD + l + 32];
    const float M3c = g_M3[n*CG + c];
    const float* xc  = x + (size_t)n*NELEM + (size_t)c*HW;
    const float* x3c = &g_x3[(size_t)(n*CG + c)*HW];

    float s = 0.f, sq = 0.f, mx = -1e30f, mn = 1e30f, z3 = 0.f;
    for (int r = 0; r < HH; r++) {
        float ahr = ahs[c*HH + r];
        float xv0 = xc[r*WWD + l], xv1 = xc[r*WWD + l + 32];
        float x1a = xv0 * (ahr * aw0), x1b = xv1 * (ahr * aw1);
        s += x1a + x1b;
        sq = fmaf(x1a, x1a, fmaf(x1b, x1b, sq));
        mx = fmaxf(mx, fmaxf(x1a, x1b));
        mn = fminf(mn, fminf(x1a, x1b));
        float t0 = x3c[r*WWD + l], t1v = x3c[r*WWD + l + 32];
        z3 += __expf(t0 - M3c) + __expf(t1v - M3c);
    }
    #pragma unroll
    for (int o = 16; o > 0; o >>= 1) {
        s  += __shfl_xor_sync(~0u, s,  o);
        sq += __shfl_xor_sync(~0u, sq, o);
        mx = fmaxf(mx, __shfl_xor_sync(~0u, mx, o));
        mn = fminf(mn, __shfl_xor_sync(~0u, mn, o));
        z3 += __shfl_xor_sync(~0u, z3, o);
    }
    if (l == 0) { r_s[c]=s; r_sq[c]=sq; r_mx[c]=mx; r_mn[c]=mn; r_z3[c]=z3; }
    __syncthreads();
    if (tid < 16) {
        float ts = 0.f, tsq = 0.f;
        for (int i = 0; i < 16; i++) { ts += r_s[i]; tsq += r_sq[i]; }
        float mu  = ts  * (1.f/65536.f);
        float var = tsq * (1.f/65536.f) - mu*mu;
        float inv = rsqrtf(var + 1e-5f);
        float a = gamma[tid] * inv;
        float M1 = (a >= 0.f) ? a * r_mx[tid] : a * r_mn[tid];
        float v1 = fmaf(a, r_s[tid]*(1.f/4096.f) - mu, beta[tid]);
        g_sc[n*CG + tid] = a;
        g_M1[n*CG + tid] = M1;
        g_v1[n*CG + tid] = v1;
        g_Z3[n*CG + tid] = r_z3[tid];
    }
}

// ---------------- K4: Z1 + fold t1/t3 ---------------------------------------
__global__ __launch_bounds__(512) void k4_z1(const float* __restrict__ x)
{
    __shared__ float ahs[CG*HH];
    __shared__ float z1s[16];
    const int n = blockIdx.x, tid = threadIdx.x;

    for (int i = tid; i < CG*HH; i += 512) ahs[i] = g_ah[n*CG*HH + i];
    __syncthreads();

    const int c = tid >> 5, l = tid & 31;
    const float sc = g_sc[n*CG + c];
    const float M1 = g_M1[n*CG + c];
    const float caw0 = sc * g_aw[(n*CG + c)*WWD + l];
    const float caw1 = sc * g_aw[(n*CG + c)*WWD + l + 32];
    const float* xc = x + (size_t)n*NELEM + (size_t)c*HW;

    float z1 = 0.f;
    for (int r = 0; r < HH; r++) {
        float ahr = ahs[c*HH + r];
        float m0 = ahr * caw0, m1 = ahr * caw1;
        z1 += __expf(fmaf(m0, xc[r*WWD + l],      -M1))
            + __expf(fmaf(m1, xc[r*WWD + l + 32], -M1));
    }
    #pragma unroll
    for (int o = 16; o > 0; o >>= 1) z1 += __shfl_xor_sync(~0u, z1, o);
    if (l == 0) z1s[c] = z1;
    __syncthreads();
    if (tid < 16) {
        g_t1[n*CG + tid] = g_v3[n*CG + tid] * __expf(-g_M1[n*CG + tid]) / z1s[tid];
        g_t3[n*CG + tid] = g_v1[n*CG + tid] * __expf(-g_M3[n*CG + tid]) / g_Z3[n*CG + tid];
    }
}

// ---------------- K5: gate + output ------------------------------------------
__global__ __launch_bounds__(512) void k5_out(const float* __restrict__ x,
                                              float* __restrict__ out)
{
    __shared__ float scs[16], t1s[16], t3s[16], ahs[16*8], aws[CG*WWD];
    const int n = blockIdx.y, s = blockIdx.x, tid = threadIdx.x;  // 512 thr, 8 rows
    const int r0 = s * 8;

    if (tid < 16) {
        scs[tid] = g_sc[n*CG + tid];
        t1s[tid] = g_t1[n*CG + tid];
        t3s[tid] = g_t3[n*CG + tid];
    }
    for (int i = tid; i < 16*8; i += 512) {
        int c = i >> 3, rr = i & 7;
        ahs[i] = g_ah[(n*CG + c)*HH + r0 + rr];
    }
    for (int i = tid; i < CG*WWD; i += 512) aws[i] = g_aw[n*CG*WWD + i];
    __syncthreads();

    const int r = tid >> 6, w = tid & 63;
    const size_t base = (size_t)n*NELEM + (size_t)(r0 + r)*WWD + w;
    const size_t b3off = (size_t)n*NELEM + (size_t)(r0 + r)*WWD + w;

    float xv[16];
    float acc = 0.f;
    #pragma unroll
    for (int c = 0; c < 16; c++) {
        float xx = x[base + (size_t)c*HW];
        xv[c] = xx;
        float x3v = g_x3[b3off + (size_t)c*HW];
        float m = scs[c] * ahs[c*8 + r] * aws[c*WWD + w];
        acc += t3s[c] * __expf(x3v) + t1s[c] * __expf(m * xx);
    }
    float sgm = 1.f / (1.f + __expf(-acc));
    #pragma unroll
    for (int c = 0; c < 16; c++) out[base + (size_t)c*HW] = xv[c] * sgm;
}

// ---------------- launcher ----------------------------------------------------
extern "C" void kernel_launch(void* const* d_in, const int* in_sizes, int n_in,
                              void* d_out, int out_size)
{
    const float* x     = (const float*)d_in[0];
    const float* w1    = (const float*)d_in[1];
    const float* b1    = (const float*)d_in[2];
    const float* wh    = (const float*)d_in[3];
    const float* bh    = (const float*)d_in[4];
    const float* ww    = (const float*)d_in[5];
    const float* bw    = (const float*)d_in[6];
    const float* w3    = (const float*)d_in[7];
    const float* b3    = (const float*)d_in[8];
    const float* gamma = (const float*)d_in[9];
    const float* beta  = (const float*)d_in[10];
    float* out = (float*)d_out;

    const int smem1 = CG * XS_ROWS * XS_PITCH * sizeof(float);   // 78336 B
    cudaFuncSetAttribute(k1_conv, cudaFuncAttributeMaxDynamicSharedMemorySize, smem1);

    k1_conv<<<dim3(4, NG), 256, smem1>>>(x, w3, b3);
    k2_small<<<NG, 128>>>(w1, b1, wh, bh, ww, bw);
    k3_stats<<<NG, 512>>>(x, gamma, beta);
    k4_z1<<<NG, 512>>>(x);
    k5_out<<<dim3(8, NG), 512>>>(x, out);
}

// round 5
// speedup vs baseline: 1.0548x; 1.0548x over previous
#include <cuda_runtime.h>
#include <cuda_bf16.h>
#include <math.h>

#define NG    1024
#define CG    16
#define HH    64
#define WWD   64
#define HW    4096
#define NELEM (CG*HW)   // 65536 floats per group

// ---------------- scratch (static device globals: no runtime alloc) ----------
__device__ __nv_bfloat16 g_x3h[(size_t)NG*CG*HW];   // 128MB conv3x3+silu cache (bf16)
__device__ float g_rowsum[NG*CG*HH];
__device__ float g_colpart[NG*4*CG*WWD];
__device__ float g_maxpart[NG*4*CG];
__device__ float g_vsumpart[NG*4*CG];
__device__ float g_ah[NG*CG*HH];
__device__ float g_aw[NG*CG*WWD];
__device__ float g_M3[NG*CG];
__device__ float g_v3[NG*CG];

// ---------------- f32x2 helpers ----------------------------------------------
__device__ __forceinline__ void ffma2(unsigned long long &d,
                                      unsigned long long a,
                                      unsigned long long b) {
    asm("fma.rn.f32x2 %0, %1, %2, %0;" : "+l"(d) : "l"(a), "l"(b));
}
__device__ __forceinline__ unsigned long long pack2(float x, float y) {
    unsigned long long r;
    asm("mov.b64 %0, {%1, %2};" : "=l"(r) : "f"(x), "f"(y));
    return r;
}
__device__ __forceinline__ unsigned long long packdup(float x) {
    unsigned long long r;
    asm("mov.b64 %0, {%1, %1};" : "=l"(r) : "f"(x));
    return r;
}
__device__ __forceinline__ void unpack2(unsigned long long v, float &x, float &y) {
    asm("mov.b64 {%0, %1}, %2;" : "=f"(x), "=f"(y) : "l"(v));
}

// ---------------- K1: conv3x3 (f32x2) + silu + row/col sums + x3 stats -------
// SMEM: two SoA fp32 tiles (row pairs split), pitch 71, per-16 pad in w.
//   s_lo[ci][i][sw]  holds x[ci][r0+i-1][w]   (i in 0..9)
//   s_hi[ci][i][sw]  holds x[ci][r0+i+7][w]
//   sw(j) = j + (j>>4),  j = w+1 in 0..65  -> sw in 0..69, pitch 71
#define PITCH 71
#define CIPLANE (10*PITCH)          // 710
#define TILEF   (CG*CIPLANE)        // 11360 floats per array

extern __shared__ float s_dyn[];

__global__ __launch_bounds__(256, 1) void k1_conv(
    const float* __restrict__ x, const float* __restrict__ w3,
    const float* __restrict__ b3)
{
    float* s_lo = s_dyn;
    float* s_hi = s_dyn + TILEF;
    float* ws   = s_dyn + 2*TILEF;   // 2304 floats, transposed [(ci*9+k)*16+co]

    const int n = blockIdx.y, s = blockIdx.x, tid = threadIdx.x;
    const float* xn = x + (size_t)n * NELEM;
    const int r0 = s * 16;

    for (int i = tid; i < CG*CG*9; i += 256) {
        int co = i / 144; int rem = i - co * 144;
        ws[rem * 16 + co] = w3[i];
    }
    // stage SoA tiles
    for (int idx = tid; idx < CG*10*WWD; idx += 256) {
        int ci = idx / 640; int rem = idx - ci*640;
        int i = rem >> 6; int w = rem & 63;
        int glo = r0 + i - 1, ghi = r0 + i + 7;
        float lo = (glo >= 0 && glo < HH) ? xn[ci*HW + glo*WWD + w] : 0.f;
        float hi = (ghi < HH) ? xn[ci*HW + ghi*WWD + w] : 0.f;
        int j = w + 1;
        int off = ci*CIPLANE + i*PITCH + j + (j >> 4);
        s_lo[off] = lo; s_hi[off] = hi;
    }
    // halo zeros at j=0 (sw 0) and j=65 (sw 69)
    for (int idx = tid; idx < CG*10; idx += 256) {
        int base = idx * PITCH;
        s_lo[base] = 0.f; s_lo[base + 69] = 0.f;
        s_hi[base] = 0.f; s_hi[base + 69] = 0.f;
    }
    __syncthreads();

    // ---- row sums (x pooled over w) ----
    {
        const int c = tid & 15, rl = tid >> 4;
        const float* arr = (rl <= 8) ? s_lo : s_hi;
        const int i = (rl <= 8) ? (rl + 1) : (rl - 7);
        const int base = c*CIPLANE + i*PITCH;
        float sum = 0.f;
        #pragma unroll
        for (int w = 0; w < WWD; w++) {
            int j = w + 1;
            sum += arr[base + j + (j >> 4)];
        }
        g_rowsum[(n*CG + c)*HH + (r0 + rl)] = sum;
    }
    // ---- col partial sums ----
    for (int k = 0; k < 4; k++) {
        int id = tid + k*256;
        int c = id >> 6, w = id & 63;
        int j = w + 1; int sw = j + (j >> 4);
        float sum = 0.f;
        #pragma unroll
        for (int rr = 0; rr < 16; rr++) {
            const float* arr = (rr <= 8) ? s_lo : s_hi;
            const int i = (rr <= 8) ? (rr + 1) : (rr - 7);
            sum += arr[c*CIPLANE + i*PITCH + sw];
        }
        g_colpart[((n*4 + s)*CG + c)*WWD + w] = sum;
    }

    // ---- conv: warp cp handles co pair {2cp, 2cp+1}; lane = (r, wq) ----
    const int cp = tid >> 5, lane = tid & 31;
    const int r = lane >> 2, wq = lane & 3;
    const int woff = wq * 17;

    unsigned long long acc[2][16];
    #pragma unroll
    for (int cl = 0; cl < 2; cl++)
        #pragma unroll
        for (int t = 0; t < 16; t++) acc[cl][t] = 0ULL;

    #pragma unroll 1
    for (int ci = 0; ci < CG; ci++) {
        const int cibase = ci * CIPLANE;
        #pragma unroll
        for (int dr = 0; dr < 3; dr++) {
            const int rowb = cibase + (r + dr)*PITCH + woff;
            unsigned long long v[18];
            #pragma unroll
            for (int k = 0; k < 18; k++) {
                int idx2 = rowb + k + (k >= 16 ? 1 : 0);
                float lo = s_lo[idx2], hi = s_hi[idx2];
                v[k] = pack2(lo, hi);
            }
            const int wb = (ci*9 + dr*3) * 16;
            #pragma unroll
            for (int cl = 0; cl < 2; cl++) {
                const int co = cp*2 + cl;
                unsigned long long wp0 = packdup(ws[wb + co]);
                unsigned long long wp1 = packdup(ws[wb + 16 + co]);
                unsigned long long wp2 = packdup(ws[wb + 32 + co]);
                #pragma unroll
                for (int t = 0; t < 16; t++) {
                    ffma2(acc[cl][t], wp0, v[t]);
                    ffma2(acc[cl][t], wp1, v[t+1]);
                    ffma2(acc[cl][t], wp2, v[t+2]);
                }
            }
        }
    }

    // ---- epilogue: bias + silu + bf16 store + per-co strip stats ----
    #pragma unroll
    for (int cl = 0; cl < 2; cl++) {
        const int co = cp*2 + cl;
        const float bco = __ldg(&b3[co]);
        __nv_bfloat16* o0 = &g_x3h[(size_t)(n*CG + co)*HW + (size_t)(r0 + r)*WWD + wq*16];
        __nv_bfloat16* o1 = o0 + 8*WWD;
        float vmax = -1e30f, vsum = 0.f;
        #pragma unroll
        for (int t = 0; t < 16; t++) {
            float z0, z1;
            unpack2(acc[cl][t], z0, z1);
            z0 += bco; z1 += bco;
            float s0 = z0 / (1.f + __expf(-z0));
            float s1 = z1 / (1.f + __expf(-z1));
            o0[t] = __float2bfloat16(s0);
            o1[t] = __float2bfloat16(s1);
            vmax = fmaxf(vmax, fmaxf(s0, s1));
            vsum += s0 + s1;
        }
        #pragma unroll
        for (int o = 16; o > 0; o >>= 1) {
            vmax = fmaxf(vmax, __shfl_xor_sync(~0u, vmax, o));
            vsum += __shfl_xor_sync(~0u, vsum, o);
        }
        if (lane == 0) {
            g_maxpart[(n*4 + s)*CG + co] = vmax;
            g_vsumpart[(n*4 + s)*CG + co] = vsum;
        }
    }
}

// ---------------- K2: small matmuls (y, a_h, a_w) + x3 stat finalize ---------
__global__ __launch_bounds__(128) void k2_small(
    const float* __restrict__ w1, const float* __restrict__ b1,
    const float* __restrict__ wh, const float* __restrict__ bh,
    const float* __restrict__ ww, const float* __restrict__ bw)
{
    __shared__ float W1s[256], Whs[256], Wws[256], b1s[16], bhs[16], bws[16];
    const int n = blockIdx.x, tid = threadIdx.x;

    for (int i = tid; i < 256; i += 128) { W1s[i] = w1[i]; Whs[i] = wh[i]; Wws[i] = ww[i]; }
    if (tid < 16) { b1s[tid] = b1[tid]; bhs[tid] = bh[tid]; bws[tid] = bw[tid]; }
    __syncthreads();

    const int pos = tid;
    float xcol[16];
    if (pos < 64) {
        #pragma unroll
        for (int ci = 0; ci < 16; ci++)
            xcol[ci] = g_rowsum[(n*CG + ci)*HH + pos] * (1.f/64.f);
    } else {
        const int w = pos - 64;
        #pragma unroll
        for (int ci = 0; ci < 16; ci++) {
            float sv = 0.f;
            for (int st = 0; st < 4; st++)
                sv += g_colpart[((n*4 + st)*CG + ci)*WWD + w];
            xcol[ci] = sv * (1.f/64.f);
        }
    }
    float y[16];
    #pragma unroll
    for (int o = 0; o < 16; o++) {
        float t = b1s[o];
        #pragma unroll
        for (int ci = 0; ci < 16; ci++) t = fmaf(W1s[o*16 + ci], xcol[ci], t);
        y[o] = t / (1.f + __expf(-t));
    }
    if (pos < 64) {
        #pragma unroll
        for (int o = 0; o < 16; o++) {
            float t = bhs[o];
            #pragma unroll
            for (int ci = 0; ci < 16; ci++) t = fmaf(Whs[o*16 + ci], y[ci], t);
            g_ah[(n*CG + o)*HH + pos] = 1.f / (1.f + __expf(-t));
        }
    } else {
        const int w = pos - 64;
        #pragma unroll
        for (int o = 0; o < 16; o++) {
            float t = bws[o];
            #pragma unroll
            for (int ci = 0; ci < 16; ci++) t = fmaf(Wws[o*16 + ci], y[ci], t);
            g_aw[(n*CG + o)*WWD + w] = 1.f / (1.f + __expf(-t));
        }
    }
    if (tid < 16) {
        float m = -1e30f, vs = 0.f;
        for (int st = 0; st < 4; st++) {
            m = fmaxf(m, g_maxpart[(n*4 + st)*CG + tid]);
            vs += g_vsumpart[(n*4 + st)*CG + tid];
        }
        g_M3[n*CG + tid] = m;
        g_v3[n*CG + tid] = vs * (1.f/4096.f);
    }
}

// ---------------- K345: fused stats + Z1 + gate + output ---------------------
__global__ __launch_bounds__(512) void k345(
    const float* __restrict__ x, const float* __restrict__ gamma,
    const float* __restrict__ beta, float* __restrict__ out)
{
    __shared__ float ahs[CG*HH], aws[CG*WWD];
    __shared__ float r_s[16], r_sq[16], r_mx[16], r_mn[16], r_z3[16], r_z1[16];
    __shared__ float s_sc[16], s_M1[16], s_t1[16], s_t3[16];

    const int n = blockIdx.x, tid = threadIdx.x;   // 512 = 16 warps

    for (int i = tid; i < CG*HH; i += 512) ahs[i] = g_ah[n*CG*HH + i];
    for (int i = tid; i < CG*WWD; i += 512) aws[i] = g_aw[n*CG*WWD + i];
    __syncthreads();

    const int c = tid >> 5, l = tid & 31;
    const float aw0 = aws[c*WWD + l];
    const float aw1 = aws[c*WWD + l + 32];
    const float M3c = g_M3[n*CG + c];
    const float* xc = x + (size_t)n*NELEM + (size_t)c*HW;
    const __nv_bfloat16* x3c = &g_x3h[(size_t)(n*CG + c)*HW];

    // ---- pass A: x1 stats + Z3 ----
    {
        float sum = 0.f, sq = 0.f, mx = -1e30f, mn = 1e30f, z3 = 0.f;
        for (int r = 0; r < HH; r++) {
            float ahr = ahs[c*HH + r];
            float xv0 = xc[r*WWD + l], xv1 = xc[r*WWD + l + 32];
            float x1a = xv0 * (ahr * aw0), x1b = xv1 * (ahr * aw1);
            sum += x1a + x1b;
            sq = fmaf(x1a, x1a, fmaf(x1b, x1b, sq));
            mx = fmaxf(mx, fmaxf(x1a, x1b));
            mn = fminf(mn, fminf(x1a, x1b));
            float t0 = __bfloat162float(x3c[r*WWD + l]);
            float t1v = __bfloat162float(x3c[r*WWD + l + 32]);
            z3 += __expf(t0 - M3c) + __expf(t1v - M3c);
        }
        #pragma unroll
        for (int o = 16; o > 0; o >>= 1) {
            sum += __shfl_xor_sync(~0u, sum, o);
            sq  += __shfl_xor_sync(~0u, sq, o);
            mx = fmaxf(mx, __shfl_xor_sync(~0u, mx, o));
            mn = fminf(mn, __shfl_xor_sync(~0u, mn, o));
            z3 += __shfl_xor_sync(~0u, z3, o);
        }
        if (l == 0) { r_s[c]=sum; r_sq[c]=sq; r_mx[c]=mx; r_mn[c]=mn; r_z3[c]=z3; }
    }
    __syncthreads();
    if (tid < 16) {
        float ts = 0.f, tsq = 0.f;
        for (int i = 0; i < 16; i++) { ts += r_s[i]; tsq += r_sq[i]; }
        float mu  = ts  * (1.f/65536.f);
        float var = tsq * (1.f/65536.f) - mu*mu;
        float inv = rsqrtf(var + 1e-5f);
        float a = gamma[tid] * inv;
        float M1 = (a >= 0.f) ? a * r_mx[tid] : a * r_mn[tid];
        s_sc[tid] = a;
        s_M1[tid] = M1;
        // v1 stored temporarily in r_s
        r_s[tid] = fmaf(a, r_s[tid]*(1.f/4096.f) - mu, beta[tid]);
    }
    __syncthreads();

    // ---- pass B: Z1 ----
    {
        const float sc = s_sc[c], M1 = s_M1[c];
        const float caw0 = sc * aw0, caw1 = sc * aw1;
        float z1 = 0.f;
        for (int r = 0; r < HH; r++) {
            float ahr = ahs[c*HH + r];
            float m0 = ahr * caw0, m1 = ahr * caw1;
            z1 += __expf(fmaf(m0, xc[r*WWD + l],      -M1))
                + __expf(fmaf(m1, xc[r*WWD + l + 32], -M1));
        }
        #pragma unroll
        for (int o = 16; o > 0; o >>= 1) z1 += __shfl_xor_sync(~0u, z1, o);
        if (l == 0) r_z1[c] = z1;
    }
    __syncthreads();
    if (tid < 16) {
        s_t1[tid] = g_v3[n*CG + tid] * __expf(-s_M1[tid]) / r_z1[tid];
        s_t3[tid] = r_s[tid] * __expf(-g_M3[n*CG + tid]) / r_z3[tid];
    }
    __syncthreads();

    // ---- pass C: gate + output ----
    const float* xg = x + (size_t)n*NELEM;
    const __nv_bfloat16* x3g = &g_x3h[(size_t)n*NELEM];
    float* og = out + (size_t)n*NELEM;

    for (int it = 0; it < 8; it++) {
        const int p = it*512 + tid;
        const int r = p >> 6, w = p & 63;
        float xv[16];
        float acc = 0.f;
        #pragma unroll
        for (int cc = 0; cc < 16; cc++) {
            float xx = xg[(size_t)cc*HW + p];
            xv[cc] = xx;
            float x3v = __bfloat162float(x3g[(size_t)cc*HW + p]);
            float m = s_sc[cc] * ahs[cc*HH + r] * aws[cc*WWD + w];
            acc += s_t3[cc] * __expf(x3v) + s_t1[cc] * __expf(m * xx);
        }
        float sgm = 1.f / (1.f + __expf(-acc));
        #pragma unroll
        for (int cc = 0; cc < 16; cc++) og[(size_t)cc*HW + p] = xv[cc] * sgm;
    }
}

// ---------------- launcher ----------------------------------------------------
extern "C" void kernel_launch(void* const* d_in, const int* in_sizes, int n_in,
                              void* d_out, int out_size)
{
    const float* x     = (const float*)d_in[0];
    const float* w1    = (const float*)d_in[1];
    const float* b1    = (const float*)d_in[2];
    const float* wh    = (const float*)d_in[3];
    const float* bh    = (const float*)d_in[4];
    const float* ww    = (const float*)d_in[5];
    const float* bw    = (const float*)d_in[6];
    const float* w3    = (const float*)d_in[7];
    const float* b3    = (const float*)d_in[8];
    const float* gamma = (const float*)d_in[9];
    const float* beta  = (const float*)d_in[10];
    float* out = (float*)d_out;

    const int smem1 = (2*TILEF + CG*CG*9) * sizeof(float);   // ~100 KB
    static int attr_set = 0;
    cudaFuncSetAttribute(k1_conv, cudaFuncAttributeMaxDynamicSharedMemorySize, smem1);
    (void)attr_set;

    k1_conv<<<dim3(4, NG), 256, smem1>>>(x, w3, b3);
    k2_small<<<NG, 128>>>(w1, b1, wh, bh, ww, bw);
    k345<<<NG, 512>>>(x, gamma, beta, out);
}

// round 6
// speedup vs baseline: 1.3909x; 1.3187x over previous
#include <cuda_runtime.h>
#include <cuda_bf16.h>
#include <math.h>

#define NG    1024
#define CG    16
#define HH    64
#define WWD   64
#define HW    4096
#define NELEM (CG*HW)   // 65536 floats per group

// ---------------- scratch (static device globals: no runtime alloc) ----------
__device__ __nv_bfloat16 g_x3h[(size_t)NG*CG*HW];   // 128MB conv3x3+silu cache (bf16)
__device__ float g_rowsum[NG*CG*HH];
__device__ float g_colpart[NG*8*CG*WWD];
__device__ float g_maxpart[NG*8*CG];
__device__ float g_vsumpart[NG*8*CG];
__device__ float g_ah[NG*CG*HH];
__device__ float g_aw[NG*CG*WWD];
__device__ float g_M3[NG*CG];
__device__ float g_v3[NG*CG];

// ---------------- f32x2 helpers ----------------------------------------------
__device__ __forceinline__ void ffma2(unsigned long long &d,
                                      unsigned long long a,
                                      unsigned long long b) {
    asm("fma.rn.f32x2 %0, %1, %2, %0;" : "+l"(d) : "l"(a), "l"(b));
}
__device__ __forceinline__ unsigned long long pack2(float x, float y) {
    unsigned long long r;
    asm("mov.b64 %0, {%1, %2};" : "=l"(r) : "f"(x), "f"(y));
    return r;
}
__device__ __forceinline__ unsigned long long packdup(float x) {
    unsigned long long r;
    asm("mov.b64 %0, {%1, %1};" : "=l"(r) : "f"(x));
    return r;
}
__device__ __forceinline__ void unpack2(unsigned long long v, float &x, float &y) {
    asm("mov.b64 {%0, %1}, %2;" : "=f"(x), "=f"(y) : "l"(v));
}

// ---------------- K1: conv3x3 (f32x2) + silu + row/col sums + x3 stats -------
// 8-output-row tile. Staged rows r0-1..r0+8 as two 6-row halves interleaved in
// one row of PITCH=152 floats:
//   lo half (offset 0):  row i <-> global r0-1+i   (i=0..5)
//   hi half (offset 76): row i <-> global r0+3+i   (i=0..5)
// Inner layout sw(j) = j + (j>>3), j = w+1 in 0..65 -> sw in 0..73.
// Bank math: lane addr = 152*(r+dr) + 9*wo + const; 152=24 mod 32, 9 odd
// -> perfect residue permutation over the 32 lanes (conflict-free).
#define PITCH 152
#define HIOFF 76
#define CIP   (6*PITCH)          // 912 floats per ci
#define TILEF (CG*CIP)           // 14592 floats

extern __shared__ float s_dyn[];

__global__ __launch_bounds__(256, 3) void k1_conv(
    const float* __restrict__ x, const float* __restrict__ w3,
    const float* __restrict__ b3)
{
    float* sT = s_dyn;             // staged tile (TILEF floats)
    float* ws = s_dyn + TILEF;     // 2304 floats, transposed [(ci*9+k)*16+co]

    const int n = blockIdx.y, s = blockIdx.x, tid = threadIdx.x;
    const float* xn = x + (size_t)n * NELEM;
    const int r0 = s * 8;

    for (int i = tid; i < CG*CG*9; i += 256) {
        int co = i / 144; int rem = i - co * 144;
        ws[rem * 16 + co] = w3[i];
    }
    // stage tile
    for (int idx = tid; idx < CG*6*WWD; idx += 256) {
        int ci = idx / 384; int rem = idx - ci*384;
        int i = rem >> 6; int w = rem & 63;
        int glo = r0 - 1 + i, ghi = r0 + 3 + i;
        float lo = (glo >= 0 && glo < HH) ? xn[ci*HW + glo*WWD + w] : 0.f;
        float hi = (ghi < HH) ? xn[ci*HW + ghi*WWD + w] : 0.f;
        int j = w + 1;
        int off = ci*CIP + i*PITCH + j + (j >> 3);
        sT[off] = lo; sT[off + HIOFF] = hi;
    }
    // halo zeros: j=0 -> sw 0 ; j=65 -> sw 73
    for (int idx = tid; idx < CG*6; idx += 256) {
        int off = (idx/6)*CIP + (idx - (idx/6)*6)*PITCH;
        sT[off] = 0.f; sT[off + 73] = 0.f;
        sT[off + HIOFF] = 0.f; sT[off + HIOFF + 73] = 0.f;
    }
    __syncthreads();

    // ---- row sums ----
    if (tid < 128) {
        const int c = tid & 15, rl = tid >> 4;   // rl 0..7
        const int i = (rl <= 4) ? (rl + 1) : (rl - 3);
        const int hoff = (rl <= 4) ? 0 : HIOFF;
        const int base = c*CIP + i*PITCH + hoff;
        float sum = 0.f;
        #pragma unroll
        for (int w = 0; w < WWD; w++) {
            int j = w + 1;
            sum += sT[base + j + (j >> 3)];
        }
        g_rowsum[(n*CG + c)*HH + (r0 + rl)] = sum;
    }
    // ---- col partial sums ----
    for (int k = 0; k < 4; k++) {
        int id = tid + k*256;
        int c = id >> 6, w = id & 63;
        int j = w + 1; int sw = j + (j >> 3);
        float sum = 0.f;
        #pragma unroll
        for (int rl = 0; rl < 8; rl++) {
            const int i = (rl <= 4) ? (rl + 1) : (rl - 3);
            const int hoff = (rl <= 4) ? 0 : HIOFF;
            sum += sT[c*CIP + i*PITCH + hoff + sw];
        }
        g_colpart[((n*8 + s)*CG + c)*WWD + w] = sum;
    }

    // ---- conv: warp cp -> co pair {2cp,2cp+1}; lane = (r:4, wo:8), 8 w each;
    //      f32x2 packs output rows (r0+r, r0+r+4) ----
    const int cp = tid >> 5, lane = tid & 31;
    const int r = lane >> 3, wo = lane & 7;
    const int woff = wo * 9;

    unsigned long long acc[2][8];
    #pragma unroll
    for (int cl = 0; cl < 2; cl++)
        #pragma unroll
        for (int t = 0; t < 8; t++) acc[cl][t] = 0ULL;

    #pragma unroll 1
    for (int ci = 0; ci < CG; ci++) {
        const int cibase = ci * CIP;
        #pragma unroll
        for (int dr = 0; dr < 3; dr++) {
            const int rowb = cibase + (r + dr)*PITCH + woff;
            unsigned long long v[10];
            #pragma unroll
            for (int k = 0; k < 10; k++) {
                int idx2 = rowb + k + (k >> 3);
                v[k] = pack2(sT[idx2], sT[idx2 + HIOFF]);
            }
            const int wb = (ci*9 + dr*3) * 16;
            #pragma unroll
            for (int cl = 0; cl < 2; cl++) {
                const int co = cp*2 + cl;
                unsigned long long wp0 = packdup(ws[wb + co]);
                unsigned long long wp1 = packdup(ws[wb + 16 + co]);
                unsigned long long wp2 = packdup(ws[wb + 32 + co]);
                #pragma unroll
                for (int t = 0; t < 8; t++) {
                    ffma2(acc[cl][t], wp0, v[t]);
                    ffma2(acc[cl][t], wp1, v[t+1]);
                    ffma2(acc[cl][t], wp2, v[t+2]);
                }
            }
        }
    }

    // ---- epilogue: bias + silu + bf16 store + per-co strip stats ----
    #pragma unroll
    for (int cl = 0; cl < 2; cl++) {
        const int co = cp*2 + cl;
        const float bco = __ldg(&b3[co]);
        __nv_bfloat16* o0 = &g_x3h[(size_t)(n*CG + co)*HW + (size_t)(r0 + r)*WWD + wo*8];
        __nv_bfloat16* o1 = o0 + 4*WWD;
        float vmax = -1e30f, vsum = 0.f;
        float f0[8], f1[8];
        #pragma unroll
        for (int t = 0; t < 8; t++) {
            float z0, z1;
            unpack2(acc[cl][t], z0, z1);
            z0 += bco; z1 += bco;
            float s0 = z0 / (1.f + __expf(-z0));
            float s1 = z1 / (1.f + __expf(-z1));
            f0[t] = s0; f1[t] = s1;
            vmax = fmaxf(vmax, fmaxf(s0, s1));
            vsum += s0 + s1;
        }
        #pragma unroll
        for (int t = 0; t < 8; t += 2) {
            *reinterpret_cast<__nv_bfloat162*>(o0 + t) =
                __nv_bfloat162(__float2bfloat16(f0[t]), __float2bfloat16(f0[t+1]));
            *reinterpret_cast<__nv_bfloat162*>(o1 + t) =
                __nv_bfloat162(__float2bfloat16(f1[t]), __float2bfloat16(f1[t+1]));
        }
        #pragma unroll
        for (int o = 16; o > 0; o >>= 1) {
            vmax = fmaxf(vmax, __shfl_xor_sync(~0u, vmax, o));
            vsum += __shfl_xor_sync(~0u, vsum, o);
        }
        if (lane == 0) {
            g_maxpart[(n*8 + s)*CG + co] = vmax;
            g_vsumpart[(n*8 + s)*CG + co] = vsum;
        }
    }
}

// ---------------- K2: small matmuls (y, a_h, a_w) + x3 stat finalize ---------
__global__ __launch_bounds__(128) void k2_small(
    const float* __restrict__ w1, const float* __restrict__ b1,
    const float* __restrict__ wh, const float* __restrict__ bh,
    const float* __restrict__ ww, const float* __restrict__ bw)
{
    __shared__ float W1s[256], Whs[256], Wws[256], b1s[16], bhs[16], bws[16];
    const int n = blockIdx.x, tid = threadIdx.x;

    for (int i = tid; i < 256; i += 128) { W1s[i] = w1[i]; Whs[i] = wh[i]; Wws[i] = ww[i]; }
    if (tid < 16) { b1s[tid] = b1[tid]; bhs[tid] = bh[tid]; bws[tid] = bw[tid]; }
    __syncthreads();

    const int pos = tid;
    float xcol[16];
    if (pos < 64) {
        #pragma unroll
        for (int ci = 0; ci < 16; ci++)
            xcol[ci] = g_rowsum[(n*CG + ci)*HH + pos] * (1.f/64.f);
    } else {
        const int w = pos - 64;
        #pragma unroll
        for (int ci = 0; ci < 16; ci++) {
            float sv = 0.f;
            for (int st = 0; st < 8; st++)
                sv += g_colpart[((n*8 + st)*CG + ci)*WWD + w];
            xcol[ci] = sv * (1.f/64.f);
        }
    }
    float y[16];
    #pragma unroll
    for (int o = 0; o < 16; o++) {
        float t = b1s[o];
        #pragma unroll
        for (int ci = 0; ci < 16; ci++) t = fmaf(W1s[o*16 + ci], xcol[ci], t);
        y[o] = t / (1.f + __expf(-t));
    }
    if (pos < 64) {
        #pragma unroll
        for (int o = 0; o < 16; o++) {
            float t = bhs[o];
            #pragma unroll
            for (int ci = 0; ci < 16; ci++) t = fmaf(Whs[o*16 + ci], y[ci], t);
            g_ah[(n*CG + o)*HH + pos] = 1.f / (1.f + __expf(-t));
        }
    } else {
        const int w = pos - 64;
        #pragma unroll
        for (int o = 0; o < 16; o++) {
            float t = bws[o];
            #pragma unroll
            for (int ci = 0; ci < 16; ci++) t = fmaf(Wws[o*16 + ci], y[ci], t);
            g_aw[(n*CG + o)*WWD + w] = 1.f / (1.f + __expf(-t));
        }
    }
    if (tid < 16) {
        float m = -1e30f, vs = 0.f;
        for (int st = 0; st < 8; st++) {
            m = fmaxf(m, g_maxpart[(n*8 + st)*CG + tid]);
            vs += g_vsumpart[(n*8 + st)*CG + tid];
        }
        g_M3[n*CG + tid] = m;
        g_v3[n*CG + tid] = vs * (1.f/4096.f);
    }
}

// ---------------- K345: fused stats + Z1 + gate + output ---------------------
__global__ __launch_bounds__(512) void k345(
    const float* __restrict__ x, const float* __restrict__ gamma,
    const float* __restrict__ beta, float* __restrict__ out)
{
    __shared__ float ahs[CG*HH], aws[CG*WWD];
    __shared__ float r_s[16], r_sq[16], r_mx[16], r_mn[16], r_z3[16], r_z1[16];
    __shared__ float s_sc[16], s_M1[16], s_t1[16], s_t3[16];

    const int n = blockIdx.x, tid = threadIdx.x;   // 512 = 16 warps

    for (int i = tid; i < CG*HH; i += 512) ahs[i] = g_ah[n*CG*HH + i];
    for (int i = tid; i < CG*WWD; i += 512) aws[i] = g_aw[n*CG*WWD + i];
    __syncthreads();

    const int c = tid >> 5, l = tid & 31;
    const float aw0 = aws[c*WWD + l];
    const float aw1 = aws[c*WWD + l + 32];
    const float M3c = g_M3[n*CG + c];
    const float* xc = x + (size_t)n*NELEM + (size_t)c*HW;
    const __nv_bfloat16* x3c = &g_x3h[(size_t)(n*CG + c)*HW];

    // ---- pass A: x1 stats + Z3 ----
    {
        float sum = 0.f, sq = 0.f, mx = -1e30f, mn = 1e30f, z3 = 0.f;
        for (int r = 0; r < HH; r++) {
            float ahr = ahs[c*HH + r];
            float xv0 = xc[r*WWD + l], xv1 = xc[r*WWD + l + 32];
            float x1a = xv0 * (ahr * aw0), x1b = xv1 * (ahr * aw1);
            sum += x1a + x1b;
            sq = fmaf(x1a, x1a, fmaf(x1b, x1b, sq));
            mx = fmaxf(mx, fmaxf(x1a, x1b));
            mn = fminf(mn, fminf(x1a, x1b));
            float t0 = __bfloat162float(x3c[r*WWD + l]);
            float t1v = __bfloat162float(x3c[r*WWD + l + 32]);
            z3 += __expf(t0 - M3c) + __expf(t1v - M3c);
        }
        #pragma unroll
        for (int o = 16; o > 0; o >>= 1) {
            sum += __shfl_xor_sync(~0u, sum, o);
            sq  += __shfl_xor_sync(~0u, sq, o);
            mx = fmaxf(mx, __shfl_xor_sync(~0u, mx, o));
            mn = fminf(mn, __shfl_xor_sync(~0u, mn, o));
            z3 += __shfl_xor_sync(~0u, z3, o);
        }
        if (l == 0) { r_s[c]=sum; r_sq[c]=sq; r_mx[c]=mx; r_mn[c]=mn; r_z3[c]=z3; }
    }
    __syncthreads();
    if (tid < 16) {
        float ts = 0.f, tsq = 0.f;
        for (int i = 0; i < 16; i++) { ts += r_s[i]; tsq += r_sq[i]; }
        float mu  = ts  * (1.f/65536.f);
        float var = tsq * (1.f/65536.f) - mu*mu;
        float inv = rsqrtf(var + 1e-5f);
        float a = gamma[tid] * inv;
        float M1 = (a >= 0.f) ? a * r_mx[tid] : a * r_mn[tid];
        s_sc[tid] = a;
        s_M1[tid] = M1;
        r_s[tid] = fmaf(a, r_s[tid]*(1.f/4096.f) - mu, beta[tid]);   // v1
    }
    __syncthreads();

    // ---- pass B: Z1 ----
    {
        const float sc = s_sc[c], M1 = s_M1[c];
        const float caw0 = sc * aw0, caw1 = sc * aw1;
        float z1 = 0.f;
        for (int r = 0; r < HH; r++) {
            float ahr = ahs[c*HH + r];
            float m0 = ahr * caw0, m1 = ahr * caw1;
            z1 += __expf(fmaf(m0, xc[r*WWD + l],      -M1))
                + __expf(fmaf(m1, xc[r*WWD + l + 32], -M1));
        }
        #pragma unroll
        for (int o = 16; o > 0; o >>= 1) z1 += __shfl_xor_sync(~0u, z1, o);
        if (l == 0) r_z1[c] = z1;
    }
    __syncthreads();
    if (tid < 16) {
        s_t1[tid] = g_v3[n*CG + tid] * __expf(-s_M1[tid]) / r_z1[tid];
        s_t3[tid] = r_s[tid] * __expf(-g_M3[n*CG + tid]) / r_z3[tid];
    }
    __syncthreads();

    // ---- pass C: gate + output ----
    const float* xg = x + (size_t)n*NELEM;
    const __nv_bfloat16* x3g = &g_x3h[(size_t)n*NELEM];
    float* og = out + (size_t)n*NELEM;

    for (int it = 0; it < 8; it++) {
        const int p = it*512 + tid;
        const int r = p >> 6, w = p & 63;
        float xv[16];
        float acc = 0.f;
        #pragma unroll
        for (int cc = 0; cc < 16; cc++) {
            float xx = xg[(size_t)cc*HW + p];
            xv[cc] = xx;
            float x3v = __bfloat162float(x3g[(size_t)cc*HW + p]);
            float m = s_sc[cc] * ahs[cc*HH + r] * aws[cc*WWD + w];
            acc += s_t3[cc] * __expf(x3v) + s_t1[cc] * __expf(m * xx);
        }
        float sgm = 1.f / (1.f + __expf(-acc));
        #pragma unroll
        for (int cc = 0; cc < 16; cc++) og[(size_t)cc*HW + p] = xv[cc] * sgm;
    }
}

// ---------------- launcher ----------------------------------------------------
extern "C" void kernel_launch(void* const* d_in, const int* in_sizes, int n_in,
                              void* d_out, int out_size)
{
    const float* x     = (const float*)d_in[0];
    const float* w1    = (const float*)d_in[1];
    const float* b1    = (const float*)d_in[2];
    const float* wh    = (const float*)d_in[3];
    const float* bh    = (const float*)d_in[4];
    const float* ww    = (const float*)d_in[5];
    const float* bw    = (const float*)d_in[6];
    const float* w3    = (const float*)d_in[7];
    const float* b3    = (const float*)d_in[8];
    const float* gamma = (const float*)d_in[9];
    const float* beta  = (const float*)d_in[10];
    float* out = (float*)d_out;

    const int smem1 = (TILEF + CG*CG*9) * sizeof(float);   // 67,584 B
    cudaFuncSetAttribute(k1_conv, cudaFuncAttributeMaxDynamicSharedMemorySize, smem1);

    k1_conv<<<dim3(8, NG), 256, smem1>>>(x, w3, b3);
    k2_small<<<NG, 128>>>(w1, b1, wh, bh, ww, bw);
    k345<<<NG, 512>>>(x, gamma, beta, out);
}

// round 10
// speedup vs baseline: 1.6682x; 1.1993x over previous
#include <cuda_runtime.h>
#include <cuda_fp16.h>
#include <cuda_bf16.h>
#include <math.h>

#define NG    1024
#define CG    16
#define HH    64
#define WWD   64
#define HW    4096
#define NELEM (CG*HW)   // 65536 floats per group

// ---------------- scratch (static device globals: no runtime alloc) ----------
__device__ __nv_bfloat16 g_x3h[(size_t)NG*CG*HW];   // 128MB conv3x3+silu cache (bf16)
__device__ float g_rowsum[NG*CG*HH];
__device__ float g_colpart[NG*4*CG*WWD];
__device__ float g_z3part[NG*4*CG];
__device__ float g_vsumpart[NG*4*CG];
__device__ float g_ah[NG*CG*HH];
__device__ float g_aw[NG*CG*WWD];
__device__ float g_Z3g[NG*CG];
__device__ float g_v3[NG*CG];

// ---------------- helpers -----------------------------------------------------
__device__ __forceinline__ unsigned smem_u32(const void* p) {
    unsigned a;
    asm("{ .reg .u64 t; cvta.to.shared.u64 t, %1; cvt.u32.u64 %0, t; }"
        : "=r"(a) : "l"(p));
    return a;
}
__device__ __forceinline__ unsigned pack_h2(float a, float b) {
    __half2 h = __floats2half2_rn(a, b);
    return *reinterpret_cast<unsigned*>(&h);
}
__device__ __forceinline__ void mma16816(float d[4], const unsigned a[4],
                                         const unsigned b0, const unsigned b1) {
    asm volatile(
        "mma.sync.aligned.m16n8k16.row.col.f32.f16.f16.f32 "
        "{%0,%1,%2,%3}, {%4,%5,%6,%7}, {%8,%9}, {%0,%1,%2,%3};"
        : "+f"(d[0]), "+f"(d[1]), "+f"(d[2]), "+f"(d[3])
        : "r"(a[0]), "r"(a[1]), "r"(a[2]), "r"(a[3]), "r"(b0), "r"(b1));
}

// ---------------- K1: conv3x3 via HMMA mma.sync + silu + sums + Z3 -----------
// 16-output-row strip: stage rows r0-1..r0+16 (18) x 66 pixels x 16ci fp16.
// Pixel slot = 32B (16 ci); XOR swizzle: ci-half h lives at byte half
// h ^ ((pix>>2)&1)  -> ldmatrix conflict-free, 16B aligned.
#define SROWS 18
#define SPIX  (SROWS*66)         // 1188
#define A_BYTES (SPIX*32)        // 38016
#define SB_OFF  A_BYTES
#define SB_BYTES (9*2*32*2*4)    // 4608
#define K1_SMEM (A_BYTES + SB_BYTES)

__global__ __launch_bounds__(128, 5) void k1_conv(
    const float* __restrict__ x, const float* __restrict__ w3,
    const float* __restrict__ b3)
{
    extern __shared__ __align__(128) unsigned char sm[];
    __shared__ float s_v[16], s_z[16], s_b3[16];

    const int n = blockIdx.y, s = blockIdx.x, tid = threadIdx.x;
    const int wid = tid >> 5, lane = tid & 31;
    const int r0 = s * 16;
    const float* xn = x + (size_t)n * NELEM;

    if (tid < 16) { s_v[tid] = 0.f; s_z[tid] = 0.f; s_b3[tid] = b3[tid]; }

    // ---- B fragments in mma layout: sB[tap][nh][lane][2] ----
    {
        unsigned* sB = (unsigned*)(sm + SB_OFF);
        for (int idx = tid; idx < 9*2*32; idx += 128) {
            int tap = idx >> 6, nh = (idx >> 5) & 1, l = idx & 31;
            int g = l >> 2, t = l & 3;
            const float* wb = w3 + ((nh*8 + g)*16)*9 + tap;
            sB[idx*2    ] = pack_h2(wb[(2*t  )*9], wb[(2*t+1)*9]);
            sB[idx*2 + 1] = pack_h2(wb[(2*t+8)*9], wb[(2*t+9)*9]);
        }
    }

    // ---- stage A (fp16) + row/col sums (fp32, pre-conversion) ----
    for (int ci = wid; ci < 16; ci += 4) {
        const float* xc = xn + (size_t)ci * HW;
        const int chalf = ci >> 3, cb = (ci & 7) * 2;
        float col0 = 0.f, col1 = 0.f;
        for (int rs = 0; rs < SROWS; rs++) {
            int gr = r0 - 1 + rs;
            float v0 = 0.f, v1 = 0.f;
            if (gr >= 0 && gr < HH) {
                v0 = xc[gr*WWD + lane];
                v1 = xc[gr*WWD + lane + 32];
            }
            int p0 = rs*66 + 1 + lane, p1 = p0 + 32;
            *(__half*)(sm + p0*32 + ((chalf ^ ((p0>>2)&1))<<4) + cb) = __float2half(v0);
            *(__half*)(sm + p1*32 + ((chalf ^ ((p1>>2)&1))<<4) + cb) = __float2half(v1);
            if (rs >= 1 && rs <= 16) {
                col0 += v0; col1 += v1;
                float rsum = v0 + v1;
                #pragma unroll
                for (int o = 16; o > 0; o >>= 1) rsum += __shfl_xor_sync(~0u, rsum, o);
                if (lane == 0) g_rowsum[(n*CG + ci)*HH + r0 + rs - 1] = rsum;
            }
        }
        g_colpart[((n*4 + s)*CG + ci)*WWD + lane]      = col0;
        g_colpart[((n*4 + s)*CG + ci)*WWD + lane + 32] = col1;
        if (lane < SROWS) {
            int pa = lane*66, pb = lane*66 + 65;
            *(__half*)(sm + pa*32 + ((chalf ^ ((pa>>2)&1))<<4) + cb) = __float2half(0.f);
            *(__half*)(sm + pb*32 + ((chalf ^ ((pb>>2)&1))<<4) + cb) = __float2half(0.f);
        }
    }
    __syncthreads();

    // ---- preload B fragments into registers ----
    unsigned Br[9][2][2];
    {
        const unsigned* sB = (const unsigned*)(sm + SB_OFF);
        #pragma unroll
        for (int tap = 0; tap < 9; tap++)
            #pragma unroll
            for (int nh = 0; nh < 2; nh++) {
                int base = ((tap*2 + nh)*32 + lane)*2;
                Br[tap][nh][0] = sB[base];
                Br[tap][nh][1] = sB[base + 1];
            }
    }

    const unsigned smbase = smem_u32(sm);
    const int rowl = (lane < 16) ? lane : lane - 16;
    const int ch = lane >> 4;
    const int g = lane >> 2, t = lane & 3;

    float vs[4] = {0.f,0.f,0.f,0.f}, zs[4] = {0.f,0.f,0.f,0.f};
    float bco[4];
    #pragma unroll
    for (int i = 0; i < 4; i++) bco[i] = s_b3[(i>>1)*8 + t*2 + (i&1)];

    #pragma unroll 1
    for (int ti = 0; ti < 16; ti++) {
        const int rs = 1 + wid + (ti & 3)*4;
        const int seg = ti >> 2;
        const int p0 = rs*66 + 1 + seg*16;
        float d0[4] = {0.f,0.f,0.f,0.f}, d1[4] = {0.f,0.f,0.f,0.f};
        const int pixbase = p0 + rowl - 67;
        #pragma unroll
        for (int tap = 0; tap < 9; tap++) {
            const int dr = tap/3, dw = tap - dr*3;
            const int pix = pixbase + dr*66 + dw;
            unsigned addr = smbase + pix*32 + (((ch ^ (pix>>2)) & 1) << 4);
            unsigned a[4];
            asm volatile("ldmatrix.sync.aligned.m8n8.x4.shared.b16 {%0,%1,%2,%3}, [%4];"
                         : "=r"(a[0]), "=r"(a[1]), "=r"(a[2]), "=r"(a[3]) : "r"(addr));
            mma16816(d0, a, Br[tap][0][0], Br[tap][0][1]);
            mma16816(d1, a, Br[tap][1][0], Br[tap][1][1]);
        }
        // epilogue: bias + silu + bf16 store + vsum/z3 stats
        const int row = r0 + rs - 1;
        const int wb = seg*16 + g;
        __nv_bfloat16* ob = g_x3h + (size_t)n*NELEM + row*WWD;
        #pragma unroll
        for (int nh = 0; nh < 2; nh++) {
            const float* d = nh ? d1 : d0;
            #pragma unroll
            for (int j = 0; j < 4; j++) {
                int co = nh*8 + t*2 + (j & 1);
                int wi = wb + ((j >= 2) ? 8 : 0);
                float z = d[j] + bco[nh*2 + (j & 1)];
                float sv = z / (1.f + __expf(-z));
                ob[(size_t)co*HW + wi] = __float2bfloat16(sv);
                vs[nh*2 + (j & 1)] += sv;
                zs[nh*2 + (j & 1)] += __expf(sv);
            }
        }
    }

    // ---- stat reduction: lanes sharing t hold same co set ----
    #pragma unroll
    for (int i = 0; i < 4; i++) {
        #pragma unroll
        for (int mask = 4; mask <= 16; mask <<= 1) {
            vs[i] += __shfl_xor_sync(~0u, vs[i], mask);
            zs[i] += __shfl_xor_sync(~0u, zs[i], mask);
        }
    }
    if (lane < 4) {
        #pragma unroll
        for (int i = 0; i < 4; i++) {
            int co = (i>>1)*8 + lane*2 + (i&1);
            atomicAdd(&s_v[co], vs[i]);
            atomicAdd(&s_z[co], zs[i]);
        }
    }
    __syncthreads();
    if (tid < 16) {
        g_vsumpart[(n*4 + s)*CG + tid] = s_v[tid];
        g_z3part[(n*4 + s)*CG + tid]   = s_z[tid];
    }
}

// ---------------- K2: small matmuls (y, a_h, a_w) + x3 stat finalize ---------
__global__ __launch_bounds__(128) void k2_small(
    const float* __restrict__ w1, const float* __restrict__ b1,
    const float* __restrict__ wh, const float* __restrict__ bh,
    const float* __restrict__ ww, const float* __restrict__ bw)
{
    __shared__ float W1s[256], Whs[256], Wws[256], b1s[16], bhs[16], bws[16];
    const int n = blockIdx.x, tid = threadIdx.x;

    for (int i = tid; i < 256; i += 128) { W1s[i] = w1[i]; Whs[i] = wh[i]; Wws[i] = ww[i]; }
    if (tid < 16) { b1s[tid] = b1[tid]; bhs[tid] = bh[tid]; bws[tid] = bw[tid]; }
    __syncthreads();

    const int pos = tid;
    float xcol[16];
    if (pos < 64) {
        #pragma unroll
        for (int ci = 0; ci < 16; ci++)
            xcol[ci] = g_rowsum[(n*CG + ci)*HH + pos] * (1.f/64.f);
    } else {
        const int w = pos - 64;
        #pragma unroll
        for (int ci = 0; ci < 16; ci++) {
            float sv = 0.f;
            for (int st = 0; st < 4; st++)
                sv += g_colpart[((n*4 + st)*CG + ci)*WWD + w];
            xcol[ci] = sv * (1.f/64.f);
        }
    }
    float y[16];
    #pragma unroll
    for (int o = 0; o < 16; o++) {
        float t = b1s[o];
        #pragma unroll
        for (int ci = 0; ci < 16; ci++) t = fmaf(W1s[o*16 + ci], xcol[ci], t);
        y[o] = t / (1.f + __expf(-t));
    }
    if (pos < 64) {
        #pragma unroll
        for (int o = 0; o < 16; o++) {
            float t = bhs[o];
            #pragma unroll
            for (int ci = 0; ci < 16; ci++) t = fmaf(Whs[o*16 + ci], y[ci], t);
            g_ah[(n*CG + o)*HH + pos] = 1.f / (1.f + __expf(-t));
        }
    } else {
        const int w = pos - 64;
        #pragma unroll
        for (int o = 0; o < 16; o++) {
            float t = bws[o];
            #pragma unroll
            for (int ci = 0; ci < 16; ci++) t = fmaf(Wws[o*16 + ci], y[ci], t);
            g_aw[(n*CG + o)*WWD + w] = 1.f / (1.f + __expf(-t));
        }
    }
    if (tid < 16) {
        float z = 0.f, vs = 0.f;
        for (int st = 0; st < 4; st++) {
            z  += g_z3part[(n*4 + st)*CG + tid];
            vs += g_vsumpart[(n*4 + st)*CG + tid];
        }
        g_Z3g[n*CG + tid] = z;
        g_v3[n*CG + tid] = vs * (1.f/4096.f);
    }
}

// ---------------- K345: fused stats + Z1 + gate + output ---------------------
__global__ __launch_bounds__(512) void k345(
    const float* __restrict__ x, const float* __restrict__ gamma,
    const float* __restrict__ beta, float* __restrict__ out)
{
    __shared__ float ahs[CG*HH], aws[CG*WWD];
    __shared__ float r_s[16], r_sq[16], r_z1[16];
    __shared__ float s_sc[16], s_t1[16], s_t3[16];

    const int n = blockIdx.x, tid = threadIdx.x;   // 512 = 16 warps

    for (int i = tid; i < CG*HH; i += 512) ahs[i] = g_ah[n*CG*HH + i];
    for (int i = tid; i < CG*WWD; i += 512) aws[i] = g_aw[n*CG*WWD + i];
    __syncthreads();

    const int c = tid >> 5, l = tid & 31;
    const float aw0 = aws[c*WWD + l];
    const float aw1 = aws[c*WWD + l + 32];
    const float* xc = x + (size_t)n*NELEM + (size_t)c*HW;

    // ---- pass A: x1 sum / sumsq only ----
    {
        float sum = 0.f, sq = 0.f;
        for (int r = 0; r < HH; r++) {
            float ahr = ahs[c*HH + r];
            float x1a = xc[r*WWD + l]      * (ahr * aw0);
            float x1b = xc[r*WWD + l + 32] * (ahr * aw1);
            sum += x1a + x1b;
            sq = fmaf(x1a, x1a, fmaf(x1b, x1b, sq));
        }
        #pragma unroll
        for (int o = 16; o > 0; o >>= 1) {
            sum += __shfl_xor_sync(~0u, sum, o);
            sq  += __shfl_xor_sync(~0u, sq, o);
        }
        if (l == 0) { r_s[c] = sum; r_sq[c] = sq; }
    }
    __syncthreads();
    if (tid < 16) {
        float ts = 0.f, tsq = 0.f;
        for (int i = 0; i < 16; i++) { ts += r_s[i]; tsq += r_sq[i]; }
        float mu  = ts  * (1.f/65536.f);
        float var = tsq * (1.f/65536.f) - mu*mu;
        float a = gamma[tid] * rsqrtf(var + 1e-5f);
        s_sc[tid] = a;
        r_s[tid] = fmaf(a, r_s[tid]*(1.f/4096.f) - mu, beta[tid]);   // v1
    }
    __syncthreads();

    // ---- pass B: Z1 (no max subtraction) ----
    {
        const float sc = s_sc[c];
        const float caw0 = sc * aw0, caw1 = sc * aw1;
        float z1 = 0.f;
        for (int r = 0; r < HH; r++) {
            float ahr = ahs[c*HH + r];
            z1 += __expf(ahr * caw0 * xc[r*WWD + l])
                + __expf(ahr * caw1 * xc[r*WWD + l + 32]);
        }
        #pragma unroll
        for (int o = 16; o > 0; o >>= 1) z1 += __shfl_xor_sync(~0u, z1, o);
        if (l == 0) r_z1[c] = z1;
    }
    __syncthreads();
    if (tid < 16) {
        s_t1[tid] = g_v3[n*CG + tid] / r_z1[tid];
        s_t3[tid] = r_s[tid] / g_Z3g[n*CG + tid];
    }
    __syncthreads();

    // ---- pass C: gate + output ----
    const float* xg = x + (size_t)n*NELEM;
    const __nv_bfloat16* x3g = &g_x3h[(size_t)n*NELEM];
    float* og = out + (size_t)n*NELEM;

    for (int it = 0; it < 8; it++) {
        const int p = it*512 + tid;
        const int r = p >> 6, w = p & 63;
        float xv[16];
        float acc = 0.f;
        #pragma unroll
        for (int cc = 0; cc < 16; cc++) {
            float xx = xg[(size_t)cc*HW + p];
            xv[cc] = xx;
            float x3v = __bfloat162float(x3g[(size_t)cc*HW + p]);
            float m = s_sc[cc] * ahs[cc*HH + r] * aws[cc*WWD + w];
            acc += s_t3[cc] * __expf(x3v) + s_t1[cc] * __expf(m * xx);
        }
        float sgm = 1.f / (1.f + __expf(-acc));
        #pragma unroll
        for (int cc = 0; cc < 16; cc++) og[(size_t)cc*HW + p] = xv[cc] * sgm;
    }
}

// ---------------- launcher ----------------------------------------------------
extern "C" void kernel_launch(void* const* d_in, const int* in_sizes, int n_in,
                              void* d_out, int out_size)
{
    const float* x     = (const float*)d_in[0];
    const float* w1    = (const float*)d_in[1];
    const float* b1    = (const float*)d_in[2];
    const float* wh    = (const float*)d_in[3];
    const float* bh    = (const float*)d_in[4];
    const float* ww    = (const float*)d_in[5];
    const float* bw    = (const float*)d_in[6];
    const float* w3    = (const float*)d_in[7];
    const float* b3    = (const float*)d_in[8];
    const float* gamma = (const float*)d_in[9];
    const float* beta  = (const float*)d_in[10];
    float* out = (float*)d_out;

    cudaFuncSetAttribute(k1_conv, cudaFuncAttributeMaxDynamicSharedMemorySize, K1_SMEM);

    k1_conv<<<dim3(4, NG), 128, K1_SMEM>>>(x, w3, b3);
    k2_small<<<NG, 128>>>(w1, b1, wh, bh, ww, bw);
    k345<<<NG, 512>>>(x, gamma, beta, out);
}

// round 13
// speedup vs baseline: 2.1858x; 1.3103x over previous
#include <cuda_runtime.h>
#include <cuda_fp16.h>
#include <cuda_bf16.h>
#include <math.h>

#define NG    1024
#define CG    16
#define HH    64
#define WWD   64
#define HW    4096
#define NELEM (CG*HW)   // 65536 floats per group

// ---------------- scratch (static device globals: no runtime alloc) ----------
__device__ __nv_bfloat16 g_x3h[(size_t)NG*CG*HW];   // 128MB conv3x3+silu cache (bf16)
__device__ float g_rowsum[NG*CG*HH];
__device__ float g_colpart[NG*4*CG*WWD];
__device__ float g_z3part[NG*4*CG];
__device__ float g_vsumpart[NG*4*CG];
__device__ float g_ah[NG*CG*HH];
__device__ float g_aw[NG*CG*WWD];
__device__ float g_Z3g[NG*CG];
__device__ float g_v3[NG*CG];

// ---------------- helpers -----------------------------------------------------
__device__ __forceinline__ unsigned smem_u32(const void* p) {
    unsigned a;
    asm("{ .reg .u64 t; cvta.to.shared.u64 t, %1; cvt.u32.u64 %0, t; }"
        : "=r"(a) : "l"(p));
    return a;
}
__device__ __forceinline__ unsigned pack_h2(float a, float b) {
    __half2 h = __floats2half2_rn(a, b);
    return *reinterpret_cast<unsigned*>(&h);
}
__device__ __forceinline__ void mma16816(float d[4], const unsigned a[4],
                                         const unsigned b0, const unsigned b1) {
    asm volatile(
        "mma.sync.aligned.m16n8k16.row.col.f32.f16.f16.f32 "
        "{%0,%1,%2,%3}, {%4,%5,%6,%7}, {%8,%9}, {%0,%1,%2,%3};"
        : "+f"(d[0]), "+f"(d[1]), "+f"(d[2]), "+f"(d[3])
        : "r"(a[0]), "r"(a[1]), "r"(a[2]), "r"(a[3]), "r"(b0), "r"(b1));
}
__device__ __forceinline__ float fast_silu(float z) {
    return __fdividef(z, 1.f + __expf(-z));
}
__device__ __forceinline__ float fast_sig(float z) {
    return __fdividef(1.f, 1.f + __expf(-z));
}

// ---------------- K1: conv3x3 via HMMA mma.sync + silu + sums + Z3 -----------
// 16-output-row strip: stage rows r0-1..r0+16 (18) x 66 pixels x 16ci fp16.
// Pixel slot = 32B (16 ci); XOR swizzle: ci-half h lives at byte half
// h ^ ((pix>>2)&1)  -> ldmatrix conflict-free, 16B aligned.
#define SROWS 18
#define SPIX  (SROWS*66)         // 1188
#define A_BYTES (SPIX*32)        // 38016
#define SB_OFF  A_BYTES
#define SB_BYTES (9*2*32*2*4)    // 4608
#define K1_SMEM (A_BYTES + SB_BYTES)

__global__ __launch_bounds__(256, 4) void k1_conv(
    const float* __restrict__ x, const float* __restrict__ w3,
    const float* __restrict__ b3)
{
    extern __shared__ __align__(128) unsigned char sm[];
    __shared__ float s_v[16], s_z[16], s_b3[16];

    const int n = blockIdx.y, s = blockIdx.x, tid = threadIdx.x;
    const int wid = tid >> 5, lane = tid & 31;
    const int r0 = s * 16;
    const float* xn = x + (size_t)n * NELEM;

    if (tid < 16) { s_v[tid] = 0.f; s_z[tid] = 0.f; s_b3[tid] = b3[tid]; }

    // ---- B fragments in mma layout: sB[tap][nh][lane][2] ----
    {
        unsigned* sB = (unsigned*)(sm + SB_OFF);
        for (int idx = tid; idx < 9*2*32; idx += 256) {
            int tap = idx >> 6, nh = (idx >> 5) & 1, l = idx & 31;
            int g = l >> 2, t = l & 3;
            const float* wb = w3 + ((nh*8 + g)*16)*9 + tap;
            sB[idx*2    ] = pack_h2(wb[(2*t  )*9], wb[(2*t+1)*9]);
            sB[idx*2 + 1] = pack_h2(wb[(2*t+8)*9], wb[(2*t+9)*9]);
        }
    }

    // ---- stage A (fp16) + row/col sums (fp32), MLP-batched rows ----
    for (int ci = wid; ci < 16; ci += 8) {
        const float* xc = xn + (size_t)ci * HW;
        const int chalf = ci >> 3, cb = (ci & 7) * 2;
        float col0 = 0.f, col1 = 0.f;
        #pragma unroll
        for (int rb = 0; rb < SROWS; rb += 6) {
            float v0[6], v1[6];
            #pragma unroll
            for (int k = 0; k < 6; k++) {
                int gr = r0 - 1 + rb + k;
                v0[k] = 0.f; v1[k] = 0.f;
                if (gr >= 0 && gr < HH) {
                    v0[k] = xc[gr*WWD + lane];
                    v1[k] = xc[gr*WWD + lane + 32];
                }
            }
            #pragma unroll
            for (int k = 0; k < 6; k++) {
                int rs = rb + k;
                int p0 = rs*66 + 1 + lane, p1 = p0 + 32;
                *(__half*)(sm + p0*32 + ((chalf ^ ((p0>>2)&1))<<4) + cb) = __float2half(v0[k]);
                *(__half*)(sm + p1*32 + ((chalf ^ ((p1>>2)&1))<<4) + cb) = __float2half(v1[k]);
                if (rs >= 1 && rs <= 16) {
                    col0 += v0[k]; col1 += v1[k];
                    float rsum = v0[k] + v1[k];
                    #pragma unroll
                    for (int o = 16; o > 0; o >>= 1) rsum += __shfl_xor_sync(~0u, rsum, o);
                    if (lane == 0) g_rowsum[(n*CG + ci)*HH + r0 + rs - 1] = rsum;
                }
            }
        }
        g_colpart[((n*4 + s)*CG + ci)*WWD + lane]      = col0;
        g_colpart[((n*4 + s)*CG + ci)*WWD + lane + 32] = col1;
        if (lane < SROWS) {
            int pa = lane*66, pb = lane*66 + 65;
            *(__half*)(sm + pa*32 + ((chalf ^ ((pa>>2)&1))<<4) + cb) = __float2half(0.f);
            *(__half*)(sm + pb*32 + ((chalf ^ ((pb>>2)&1))<<4) + cb) = __float2half(0.f);
        }
    }
    __syncthreads();

    const unsigned smbase = smem_u32(sm);
    const unsigned* sB = (const unsigned*)(sm + SB_OFF);
    const int rowl = (lane < 16) ? lane : lane - 16;
    const int ch = lane >> 4;
    const int g = lane >> 2, t = lane & 3;
    const int wlo = wid & 3, whi = wid >> 2;

    float vs[4] = {0.f,0.f,0.f,0.f}, zs[4] = {0.f,0.f,0.f,0.f};
    float bco[4];
    #pragma unroll
    for (int i = 0; i < 4; i++) bco[i] = s_b3[(i>>1)*8 + t*2 + (i&1)];

    #pragma unroll 1
    for (int ti = 0; ti < 8; ti++) {
        const int rs = 1 + wlo + (ti & 3)*4;
        const int seg = whi*2 + (ti >> 2);
        const int p0 = rs*66 + 1 + seg*16;
        float d0[4] = {0.f,0.f,0.f,0.f}, d1[4] = {0.f,0.f,0.f,0.f};
        const int pixbase = p0 + rowl - 67;
        #pragma unroll
        for (int tap = 0; tap < 9; tap++) {
            const int dr = tap/3, dw = tap - dr*3;
            const int pix = pixbase + dr*66 + dw;
            unsigned addr = smbase + pix*32 + (((ch ^ (pix>>2)) & 1) << 4);
            unsigned a[4];
            asm volatile("ldmatrix.sync.aligned.m8n8.x4.shared.b16 {%0,%1,%2,%3}, [%4];"
                         : "=r"(a[0]), "=r"(a[1]), "=r"(a[2]), "=r"(a[3]) : "r"(addr));
            const int base0 = ((tap*2    )*32 + lane)*2;
            const int base1 = ((tap*2 + 1)*32 + lane)*2;
            mma16816(d0, a, sB[base0], sB[base0 + 1]);
            mma16816(d1, a, sB[base1], sB[base1 + 1]);
        }
        // epilogue: bias + silu + bf16 store + vsum/z3 stats
        const int row = r0 + rs - 1;
        const int wb = seg*16 + g;
        __nv_bfloat16* ob = g_x3h + (size_t)n*NELEM + row*WWD;
        #pragma unroll
        for (int nh = 0; nh < 2; nh++) {
            const float* d = nh ? d1 : d0;
            #pragma unroll
            for (int j = 0; j < 4; j++) {
                int co = nh*8 + t*2 + (j & 1);
                int wi = wb + ((j >= 2) ? 8 : 0);
                float z = d[j] + bco[nh*2 + (j & 1)];
                float sv = fast_silu(z);
                ob[(size_t)co*HW + wi] = __float2bfloat16(sv);
                vs[nh*2 + (j & 1)] += sv;
                zs[nh*2 + (j & 1)] += __expf(sv);
            }
        }
    }

    // ---- stat reduction: lanes sharing t hold same co set ----
    #pragma unroll
    for (int i = 0; i < 4; i++) {
        #pragma unroll
        for (int mask = 4; mask <= 16; mask <<= 1) {
            vs[i] += __shfl_xor_sync(~0u, vs[i], mask);
            zs[i] += __shfl_xor_sync(~0u, zs[i], mask);
        }
    }
    if (lane < 4) {
        #pragma unroll
        for (int i = 0; i < 4; i++) {
            int co = (i>>1)*8 + lane*2 + (i&1);
            atomicAdd(&s_v[co], vs[i]);
            atomicAdd(&s_z[co], zs[i]);
        }
    }
    __syncthreads();
    if (tid < 16) {
        g_vsumpart[(n*4 + s)*CG + tid] = s_v[tid];
        g_z3part[(n*4 + s)*CG + tid]   = s_z[tid];
    }
}

// ---------------- K2: small matmuls (y, a_h, a_w) + x3 stat finalize ---------
__global__ __launch_bounds__(128) void k2_small(
    const float* __restrict__ w1, const float* __restrict__ b1,
    const float* __restrict__ wh, const float* __restrict__ bh,
    const float* __restrict__ ww, const float* __restrict__ bw)
{
    __shared__ float W1s[256], Whs[256], Wws[256], b1s[16], bhs[16], bws[16];
    const int n = blockIdx.x, tid = threadIdx.x;

    for (int i = tid; i < 256; i += 128) { W1s[i] = w1[i]; Whs[i] = wh[i]; Wws[i] = ww[i]; }
    if (tid < 16) { b1s[tid] = b1[tid]; bhs[tid] = bh[tid]; bws[tid] = bw[tid]; }
    __syncthreads();

    const int pos = tid;
    float xcol[16];
    if (pos < 64) {
        #pragma unroll
        for (int ci = 0; ci < 16; ci++)
            xcol[ci] = g_rowsum[(n*CG + ci)*HH + pos] * (1.f/64.f);
    } else {
        const int w = pos - 64;
        #pragma unroll
        for (int ci = 0; ci < 16; ci++) {
            float sv = 0.f;
            for (int st = 0; st < 4; st++)
                sv += g_colpart[((n*4 + st)*CG + ci)*WWD + w];
            xcol[ci] = sv * (1.f/64.f);
        }
    }
    float y[16];
    #pragma unroll
    for (int o = 0; o < 16; o++) {
        float t = b1s[o];
        #pragma unroll
        for (int ci = 0; ci < 16; ci++) t = fmaf(W1s[o*16 + ci], xcol[ci], t);
        y[o] = fast_silu(t);
    }
    if (pos < 64) {
        #pragma unroll
        for (int o = 0; o < 16; o++) {
            float t = bhs[o];
            #pragma unroll
            for (int ci = 0; ci < 16; ci++) t = fmaf(Whs[o*16 + ci], y[ci], t);
            g_ah[(n*CG + o)*HH + pos] = fast_sig(t);
        }
    } else {
        const int w = pos - 64;
        #pragma unroll
        for (int o = 0; o < 16; o++) {
            float t = bws[o];
            #pragma unroll
            for (int ci = 0; ci < 16; ci++) t = fmaf(Wws[o*16 + ci], y[ci], t);
            g_aw[(n*CG + o)*WWD + w] = fast_sig(t);
        }
    }
    if (tid < 16) {
        float z = 0.f, vs = 0.f;
        for (int st = 0; st < 4; st++) {
            z  += g_z3part[(n*4 + st)*CG + tid];
            vs += g_vsumpart[(n*4 + st)*CG + tid];
        }
        g_Z3g[n*CG + tid] = z;
        g_v3[n*CG + tid] = vs * (1.f/4096.f);
    }
}

// ---------------- K345: fused stats + Z1 + gate + output ---------------------
__global__ __launch_bounds__(512) void k345(
    const float* __restrict__ x, const float* __restrict__ gamma,
    const float* __restrict__ beta, float* __restrict__ out)
{
    __shared__ float ahs[CG*HH], aws[CG*WWD];
    __shared__ float r_s[16], r_sq[16], r_z1[16];
    __shared__ float s_sc[16], s_t1[16], s_t3[16];

    const int n = blockIdx.x, tid = threadIdx.x;   // 512 = 16 warps

    for (int i = tid; i < CG*HH; i += 512) ahs[i] = g_ah[n*CG*HH + i];
    for (int i = tid; i < CG*WWD; i += 512) aws[i] = g_aw[n*CG*WWD + i];
    __syncthreads();

    const int c = tid >> 5, l = tid & 31;
    const float aw0 = aws[c*WWD + l];
    const float aw1 = aws[c*WWD + l + 32];
    const float* xc = x + (size_t)n*NELEM + (size_t)c*HW;

    // ---- pass A: x1 sum / sumsq only ----
    {
        float sum = 0.f, sq = 0.f;
        for (int r = 0; r < HH; r++) {
            float ahr = ahs[c*HH + r];
            float x1a = xc[r*WWD + l]      * (ahr * aw0);
            float x1b = xc[r*WWD + l + 32] * (ahr * aw1);
            sum += x1a + x1b;
            sq = fmaf(x1a, x1a, fmaf(x1b, x1b, sq));
        }
        #pragma unroll
        for (int o = 16; o > 0; o >>= 1) {
            sum += __shfl_xor_sync(~0u, sum, o);
            sq  += __shfl_xor_sync(~0u, sq, o);
        }
        if (l == 0) { r_s[c] = sum; r_sq[c] = sq; }
    }
    __syncthreads();
    if (tid < 16) {
        float ts = 0.f, tsq = 0.f;
        for (int i = 0; i < 16; i++) { ts += r_s[i]; tsq += r_sq[i]; }
        float mu  = ts  * (1.f/65536.f);
        float var = tsq * (1.f/65536.f) - mu*mu;
        float a = gamma[tid] * rsqrtf(var + 1e-5f);
        s_sc[tid] = a;
        r_s[tid] = fmaf(a, r_s[tid]*(1.f/4096.f) - mu, beta[tid]);   // v1
    }
    __syncthreads();

    // ---- pass B: Z1 (no max subtraction) ----
    {
        const float sc = s_sc[c];
        const float caw0 = sc * aw0, caw1 = sc * aw1;
        float z1 = 0.f;
        for (int r = 0; r < HH; r++) {
            float ahr = ahs[c*HH + r];
            z1 += __expf(ahr * caw0 * xc[r*WWD + l])
                + __expf(ahr * caw1 * xc[r*WWD + l + 32]);
        }
        #pragma unroll
        for (int o = 16; o > 0; o >>= 1) z1 += __shfl_xor_sync(~0u, z1, o);
        if (l == 0) r_z1[c] = z1;
    }
    __syncthreads();
    if (tid < 16) {
        s_t1[tid] = g_v3[n*CG + tid] / r_z1[tid];
        s_t3[tid] = r_s[tid] / g_Z3g[n*CG + tid];
    }
    __syncthreads();

    // ---- pass C: gate + output ----
    const float* xg = x + (size_t)n*NELEM;
    const __nv_bfloat16* x3g = &g_x3h[(size_t)n*NELEM];
    float* og = out + (size_t)n*NELEM;

    for (int it = 0; it < 8; it++) {
        const int p = it*512 + tid;
        const int r = p >> 6, w = p & 63;
        float xv[16];
        float acc = 0.f;
        #pragma unroll
        for (int cc = 0; cc < 16; cc++) {
            float xx = xg[(size_t)cc*HW + p];
            xv[cc] = xx;
            float x3v = __bfloat162float(x3g[(size_t)cc*HW + p]);
            float m = s_sc[cc] * ahs[cc*HH + r] * aws[cc*WWD + w];
            acc += s_t3[cc] * __expf(x3v) + s_t1[cc] * __expf(m * xx);
        }
        float sgm = fast_sig(acc);
        #pragma unroll
        for (int cc = 0; cc < 16; cc++) og[(size_t)cc*HW + p] = xv[cc] * sgm;
    }
}

// ---------------- launcher ----------------------------------------------------
extern "C" void kernel_launch(void* const* d_in, const int* in_sizes, int n_in,
                              void* d_out, int out_size)
{
    const float* x     = (const float*)d_in[0];
    const float* w1    = (const float*)d_in[1];
    const float* b1    = (const float*)d_in[2];
    const float* wh    = (const float*)d_in[3];
    const float* bh    = (const float*)d_in[4];
    const float* ww    = (const float*)d_in[5];
    const float* bw    = (const float*)d_in[6];
    const float* w3    = (const float*)d_in[7];
    const float* b3    = (const float*)d_in[8];
    const float* gamma = (const float*)d_in[9];
    const float* beta  = (const float*)d_in[10];
    float* out = (float*)d_out;

    cudaFuncSetAttribute(k1_conv, cudaFuncAttributeMaxDynamicSharedMemorySize, K1_SMEM);

    k1_conv<<<dim3(4, NG), 256, K1_SMEM>>>(x, w3, b3);
    k2_small<<<NG, 128>>>(w1, b1, wh, bh, ww, bw);
    k345<<<NG, 512>>>(x, gamma, beta, out);
}

// round 14
// speedup vs baseline: 2.2473x; 1.0281x over previous
#include <cuda_runtime.h>
#include <cuda_fp16.h>
#include <cuda_bf16.h>
#include <math.h>

#define NG    1024
#define CG    16
#define HH    64
#define WWD   64
#define HW    4096
#define NELEM (CG*HW)   // 65536 floats per group

// ---------------- scratch (static device globals: no runtime alloc) ----------
__device__ __nv_bfloat16 g_x3h[(size_t)NG*CG*HW];   // 128MB cache of exp(silu(conv3x3))
__device__ float g_rowsum[NG*CG*HH];
__device__ float g_colpart[NG*4*CG*WWD];
__device__ float g_z3part[NG*4*CG];
__device__ float g_vsumpart[NG*4*CG];

// ---------------- helpers -----------------------------------------------------
__device__ __forceinline__ unsigned smem_u32(const void* p) {
    unsigned a;
    asm("{ .reg .u64 t; cvta.to.shared.u64 t, %1; cvt.u32.u64 %0, t; }"
        : "=r"(a) : "l"(p));
    return a;
}
__device__ __forceinline__ unsigned pack_h2(float a, float b) {
    __half2 h = __floats2half2_rn(a, b);
    return *reinterpret_cast<unsigned*>(&h);
}
__device__ __forceinline__ void mma16816(float* d, const unsigned a[4],
                                         const unsigned b0, const unsigned b1) {
    asm volatile(
        "mma.sync.aligned.m16n8k16.row.col.f32.f16.f16.f32 "
        "{%0,%1,%2,%3}, {%4,%5,%6,%7}, {%8,%9}, {%0,%1,%2,%3};"
        : "+f"(d[0]), "+f"(d[1]), "+f"(d[2]), "+f"(d[3])
        : "r"(a[0]), "r"(a[1]), "r"(a[2]), "r"(a[3]), "r"(b0), "r"(b1));
}
__device__ __forceinline__ float fast_silu(float z) {
    return __fdividef(z, 1.f + __expf(-z));
}
__device__ __forceinline__ float fast_sig(float z) {
    return __fdividef(1.f, 1.f + __expf(-z));
}

// ---------------- K1: conv3x3 via HMMA + silu + sums + exp-cache + Z3 --------
#define SROWS 18
#define SPIX  (SROWS*66)         // 1188
#define A_BYTES (SPIX*32)        // 38016
#define SB_OFF  A_BYTES
#define SB_BYTES (9*2*32*2*4)    // 4608
#define K1_SMEM (A_BYTES + SB_BYTES)

__global__ __launch_bounds__(256, 3) void k1_conv(
    const float* __restrict__ x, const float* __restrict__ w3,
    const float* __restrict__ b3)
{
    extern __shared__ __align__(128) unsigned char sm[];
    __shared__ float s_v[16], s_z[16], s_b3[16];

    const int n = blockIdx.y, s = blockIdx.x, tid = threadIdx.x;
    const int wid = tid >> 5, lane = tid & 31;
    const int r0 = s * 16;
    const float* xn = x + (size_t)n * NELEM;

    if (tid < 16) { s_v[tid] = 0.f; s_z[tid] = 0.f; s_b3[tid] = b3[tid]; }

    // ---- B fragments in mma layout: sB[tap][nh][lane][2] ----
    {
        unsigned* sB = (unsigned*)(sm + SB_OFF);
        for (int idx = tid; idx < 9*2*32; idx += 256) {
            int tap = idx >> 6, nh = (idx >> 5) & 1, l = idx & 31;
            int g2 = l >> 2, t2 = l & 3;
            const float* wb = w3 + ((nh*8 + g2)*16)*9 + tap;
            sB[idx*2    ] = pack_h2(wb[(2*t2  )*9], wb[(2*t2+1)*9]);
            sB[idx*2 + 1] = pack_h2(wb[(2*t2+8)*9], wb[(2*t2+9)*9]);
        }
    }

    // ---- stage A (fp16 pairs, STS.32) + row/col sums (fp32), MLP-batched ----
    {
        const int ci0 = wid * 2;                   // 8 warps -> pairs (0,1)..(14,15)
        const float* xa = xn + (size_t)ci0 * HW;
        const float* xb = xa + HW;
        const int chalf = ci0 >> 3, cb = (ci0 & 7) * 2;
        float cA0 = 0.f, cA1 = 0.f, cB0 = 0.f, cB1 = 0.f;
        #pragma unroll
        for (int rb = 0; rb < SROWS; rb += 6) {
            float a0[6], a1[6], b0[6], b1[6];
            #pragma unroll
            for (int k = 0; k < 6; k++) {
                int gr = r0 - 1 + rb + k;
                a0[k] = a1[k] = b0[k] = b1[k] = 0.f;
                if (gr >= 0 && gr < HH) {
                    a0[k] = xa[gr*WWD + lane];
                    a1[k] = xa[gr*WWD + lane + 32];
                    b0[k] = xb[gr*WWD + lane];
                    b1[k] = xb[gr*WWD + lane + 32];
                }
            }
            #pragma unroll
            for (int k = 0; k < 6; k++) {
                int rs = rb + k;
                int p0 = rs*66 + 1 + lane, p1 = p0 + 32;
                *(unsigned*)(sm + p0*32 + ((chalf ^ ((p0>>2)&1))<<4) + cb) = pack_h2(a0[k], b0[k]);
                *(unsigned*)(sm + p1*32 + ((chalf ^ ((p1>>2)&1))<<4) + cb) = pack_h2(a1[k], b1[k]);
                if (rs >= 1 && rs <= 16) {
                    cA0 += a0[k]; cA1 += a1[k]; cB0 += b0[k]; cB1 += b1[k];
                    float rsA = a0[k] + a1[k], rsB = b0[k] + b1[k];
                    #pragma unroll
                    for (int o = 16; o > 0; o >>= 1) {
                        rsA += __shfl_xor_sync(~0u, rsA, o);
                        rsB += __shfl_xor_sync(~0u, rsB, o);
                    }
                    if (lane == 0) {
                        g_rowsum[(n*CG + ci0    )*HH + r0 + rs - 1] = rsA;
                        g_rowsum[(n*CG + ci0 + 1)*HH + r0 + rs - 1] = rsB;
                    }
                }
            }
        }
        g_colpart[((n*4 + s)*CG + ci0)*WWD + lane]          = cA0;
        g_colpart[((n*4 + s)*CG + ci0)*WWD + lane + 32]     = cA1;
        g_colpart[((n*4 + s)*CG + ci0 + 1)*WWD + lane]      = cB0;
        g_colpart[((n*4 + s)*CG + ci0 + 1)*WWD + lane + 32] = cB1;
        if (lane < SROWS) {
            int pa = lane*66, pb = lane*66 + 65;
            *(unsigned*)(sm + pa*32 + ((chalf ^ ((pa>>2)&1))<<4) + cb) = 0u;
            *(unsigned*)(sm + pb*32 + ((chalf ^ ((pb>>2)&1))<<4) + cb) = 0u;
        }
    }
    __syncthreads();

    const unsigned smbase = smem_u32(sm);
    const unsigned* sB = (const unsigned*)(sm + SB_OFF);
    const int rowl = (lane < 16) ? lane : lane - 16;
    const int ch = lane >> 4;
    const int g = lane >> 2, t = lane & 3;
    const int wlo = wid & 3, whi = wid >> 2;

    float vs[4] = {0.f,0.f,0.f,0.f}, zs[4] = {0.f,0.f,0.f,0.f};
    float bco[4];
    #pragma unroll
    for (int i = 0; i < 4; i++) bco[i] = s_b3[(i>>1)*8 + t*2 + (i&1)];

    #pragma unroll 1
    for (int batch = 0; batch < 2; batch++) {
        const int seg = whi*2 + batch;
        int pixbase[4];
        #pragma unroll
        for (int k = 0; k < 4; k++) {
            const int rs = 1 + wlo + k*4;
            pixbase[k] = rs*66 + seg*16 + rowl - 66;
        }
        float d[4][8];
        #pragma unroll
        for (int k = 0; k < 4; k++)
            #pragma unroll
            for (int j = 0; j < 8; j++) d[k][j] = 0.f;

        #pragma unroll
        for (int tap = 0; tap < 9; tap++) {
            const int dr = tap/3, dw = tap - dr*3;
            const int dlt = dr*66 + dw;
            const int base0 = ((tap*2    )*32 + lane)*2;
            const int base1 = ((tap*2 + 1)*32 + lane)*2;
            const unsigned Br00 = sB[base0], Br01 = sB[base0 + 1];
            const unsigned Br10 = sB[base1], Br11 = sB[base1 + 1];
            #pragma unroll
            for (int k = 0; k < 4; k++) {
                const int pix = pixbase[k] + dlt;
                unsigned addr = smbase + pix*32 + (((ch ^ (pix>>2)) & 1) << 4);
                unsigned a[4];
                asm volatile("ldmatrix.sync.aligned.m8n8.x4.shared.b16 {%0,%1,%2,%3}, [%4];"
                             : "=r"(a[0]), "=r"(a[1]), "=r"(a[2]), "=r"(a[3]) : "r"(addr));
                mma16816(d[k],     a, Br00, Br01);
                mma16816(d[k] + 4, a, Br10, Br11);
            }
        }
        // epilogue: bias + silu + exp + bf16 store + stats
        #pragma unroll
        for (int k = 0; k < 4; k++) {
            const int rs = 1 + wlo + k*4;
            const int row = r0 + rs - 1;
            const int wb = seg*16 + g;
            __nv_bfloat16* ob = g_x3h + (size_t)n*NELEM + row*WWD;
            #pragma unroll
            for (int nh = 0; nh < 2; nh++) {
                #pragma unroll
                for (int j = 0; j < 4; j++) {
                    int co = nh*8 + t*2 + (j & 1);
                    int wi = wb + ((j >= 2) ? 8 : 0);
                    float z = d[k][nh*4 + j] + bco[nh*2 + (j & 1)];
                    float sv = fast_silu(z);
                    float ez = __expf(sv);
                    ob[(size_t)co*HW + wi] = __float2bfloat16(ez);
                    vs[nh*2 + (j & 1)] += sv;
                    zs[nh*2 + (j & 1)] += ez;
                }
            }
        }
    }

    // ---- stat reduction: lanes sharing t hold same co set ----
    #pragma unroll
    for (int i = 0; i < 4; i++) {
        #pragma unroll
        for (int mask = 4; mask <= 16; mask <<= 1) {
            vs[i] += __shfl_xor_sync(~0u, vs[i], mask);
            zs[i] += __shfl_xor_sync(~0u, zs[i], mask);
        }
    }
    if (lane < 4) {
        #pragma unroll
        for (int i = 0; i < 4; i++) {
            int co = (i>>1)*8 + lane*2 + (i&1);
            atomicAdd(&s_v[co], vs[i]);
            atomicAdd(&s_z[co], zs[i]);
        }
    }
    __syncthreads();
    if (tid < 16) {
        g_vsumpart[(n*4 + s)*CG + tid] = s_v[tid];
        g_z3part[(n*4 + s)*CG + tid]   = s_z[tid];
    }
}

// ---------------- K345: k2 prologue + stats + Z1 + gate + output -------------
__global__ __launch_bounds__(512) void k345(
    const float* __restrict__ x,
    const float* __restrict__ w1, const float* __restrict__ b1,
    const float* __restrict__ wh, const float* __restrict__ bh,
    const float* __restrict__ ww, const float* __restrict__ bw,
    const float* __restrict__ gamma, const float* __restrict__ beta,
    float* __restrict__ out)
{
    __shared__ float ahs[CG*HH], aws[CG*WWD];
    __shared__ float W1s[256], Whs[256], Wws[256], b1s[16], bhs[16], bws[16];
    __shared__ float r_s[16], r_sq[16], r_z1[16];
    __shared__ float s_sc[16], s_t1[16], s_t3[16], s_v3[16], s_Z3[16];

    const int n = blockIdx.x, tid = threadIdx.x;   // 512 = 16 warps

    // ---- prologue: weights + K1 stat finalize ----
    for (int i = tid; i < 256; i += 512) { W1s[i] = w1[i]; Whs[i] = wh[i]; Wws[i] = ww[i]; }
    if (tid < 16) {
        b1s[tid] = b1[tid]; bhs[tid] = bh[tid]; bws[tid] = bw[tid];
        float z = 0.f, vsum = 0.f;
        for (int st = 0; st < 4; st++) {
            z    += g_z3part[(n*4 + st)*CG + tid];
            vsum += g_vsumpart[(n*4 + st)*CG + tid];
        }
        s_Z3[tid] = z;
        s_v3[tid] = vsum * (1.f/4096.f);
    }
    __syncthreads();

    // ---- k2 body: pooled-feature MLP -> ah/aw straight into smem ----
    if (tid < 128) {
        const int pos = tid;
        float xcol[16];
        if (pos < 64) {
            #pragma unroll
            for (int ci = 0; ci < 16; ci++)
                xcol[ci] = g_rowsum[(n*CG + ci)*HH + pos] * (1.f/64.f);
        } else {
            const int w = pos - 64;
            #pragma unroll
            for (int ci = 0; ci < 16; ci++) {
                float sv = 0.f;
                for (int st = 0; st < 4; st++)
                    sv += g_colpart[((n*4 + st)*CG + ci)*WWD + w];
                xcol[ci] = sv * (1.f/64.f);
            }
        }
        float y[16];
        #pragma unroll
        for (int o = 0; o < 16; o++) {
            float t = b1s[o];
            #pragma unroll
            for (int ci = 0; ci < 16; ci++) t = fmaf(W1s[o*16 + ci], xcol[ci], t);
            y[o] = fast_silu(t);
        }
        if (pos < 64) {
            #pragma unroll
            for (int o = 0; o < 16; o++) {
                float t = bhs[o];
                #pragma unroll
                for (int ci = 0; ci < 16; ci++) t = fmaf(Whs[o*16 + ci], y[ci], t);
                ahs[o*HH + pos] = fast_sig(t);
            }
        } else {
            const int w = pos - 64;
            #pragma unroll
            for (int o = 0; o < 16; o++) {
                float t = bws[o];
                #pragma unroll
                for (int ci = 0; ci < 16; ci++) t = fmaf(Wws[o*16 + ci], y[ci], t);
                aws[o*WWD + w] = fast_sig(t);
            }
        }
    }
    __syncthreads();

    const int c = tid >> 5, l = tid & 31;
    const float aw0 = aws[c*WWD + l];
    const float aw1 = aws[c*WWD + l + 32];
    const float* xc = x + (size_t)n*NELEM + (size_t)c*HW;

    // ---- pass A: x1 sum / sumsq (2-row batches for MLP) ----
    {
        float sum = 0.f, sq = 0.f;
        #pragma unroll 2
        for (int r = 0; r < HH; r += 2) {
            float xa0 = xc[r*WWD + l],       xa1 = xc[r*WWD + l + 32];
            float xb0 = xc[(r+1)*WWD + l],   xb1 = xc[(r+1)*WWD + l + 32];
            float ha = ahs[c*HH + r], hb = ahs[c*HH + r + 1];
            float x1a = xa0 * (ha * aw0), x1b = xa1 * (ha * aw1);
            float x1c = xb0 * (hb * aw0), x1d = xb1 * (hb * aw1);
            sum += (x1a + x1b) + (x1c + x1d);
            sq = fmaf(x1a, x1a, fmaf(x1b, x1b, fmaf(x1c, x1c, fmaf(x1d, x1d, sq))));
        }
        #pragma unroll
        for (int o = 16; o > 0; o >>= 1) {
            sum += __shfl_xor_sync(~0u, sum, o);
            sq  += __shfl_xor_sync(~0u, sq, o);
        }
        if (l == 0) { r_s[c] = sum; r_sq[c] = sq; }
    }
    __syncthreads();
    if (tid < 16) {
        float ts = 0.f, tsq = 0.f;
        for (int i = 0; i < 16; i++) { ts += r_s[i]; tsq += r_sq[i]; }
        float mu  = ts  * (1.f/65536.f);
        float var = tsq * (1.f/65536.f) - mu*mu;
        float a = gamma[tid] * rsqrtf(var + 1e-5f);
        s_sc[tid] = a;
        r_s[tid] = fmaf(a, r_s[tid]*(1.f/4096.f) - mu, beta[tid]);   // v1
    }
    __syncthreads();

    // ---- pass B: Z1 (no max subtraction; 2-row batches) ----
    {
        const float sc = s_sc[c];
        const float caw0 = sc * aw0, caw1 = sc * aw1;
        float z1 = 0.f;
        #pragma unroll 2
        for (int r = 0; r < HH; r += 2) {
            float xa0 = xc[r*WWD + l],       xa1 = xc[r*WWD + l + 32];
            float xb0 = xc[(r+1)*WWD + l],   xb1 = xc[(r+1)*WWD + l + 32];
            float ha = ahs[c*HH + r], hb = ahs[c*HH + r + 1];
            z1 += __expf(ha * caw0 * xa0) + __expf(ha * caw1 * xa1)
                + __expf(hb * caw0 * xb0) + __expf(hb * caw1 * xb1);
        }
        #pragma unroll
        for (int o = 16; o > 0; o >>= 1) z1 += __shfl_xor_sync(~0u, z1, o);
        if (l == 0) r_z1[c] = z1;
    }
    __syncthreads();
    if (tid < 16) {
        s_t1[tid] = s_v3[tid] / r_z1[tid];
        s_t3[tid] = r_s[tid] / s_Z3[tid];
    }
    __syncthreads();

    // ---- pass C: gate + output (x3h holds exp(silu) already) ----
    const float* xg = x + (size_t)n*NELEM;
    const __nv_bfloat16* x3g = &g_x3h[(size_t)n*NELEM];
    float* og = out + (size_t)n*NELEM;

    for (int it = 0; it < 8; it++) {
        const int p = it*512 + tid;
        const int r = p >> 6, w = p & 63;
        float xv[16];
        float acc = 0.f;
        #pragma unroll
        for (int cc = 0; cc < 16; cc++) {
            float xx = xg[(size_t)cc*HW + p];
            xv[cc] = xx;
            float e3v = __bfloat162float(x3g[(size_t)cc*HW + p]);
            float m = s_sc[cc] * ahs[cc*HH + r] * aws[cc*WWD + w];
            acc = fmaf(s_t3[cc], e3v, fmaf(s_t1[cc], __expf(m * xx), acc));
        }
        float sgm = fast_sig(acc);
        #pragma unroll
        for (int cc = 0; cc < 16; cc++) og[(size_t)cc*HW + p] = xv[cc] * sgm;
    }
}

// ---------------- launcher ----------------------------------------------------
extern "C" void kernel_launch(void* const* d_in, const int* in_sizes, int n_in,
                              void* d_out, int out_size)
{
    const float* x     = (const float*)d_in[0];
    const float* w1    = (const float*)d_in[1];
    const float* b1    = (const float*)d_in[2];
    const float* wh    = (const float*)d_in[3];
    const float* bh    = (const float*)d_in[4];
    const float* ww    = (const float*)d_in[5];
    const float* bw    = (const float*)d_in[6];
    const float* w3    = (const float*)d_in[7];
    const float* b3    = (const float*)d_in[8];
    const float* gamma = (const float*)d_in[9];
    const float* beta  = (const float*)d_in[10];
    float* out = (float*)d_out;

    cudaFuncSetAttribute(k1_conv, cudaFuncAttributeMaxDynamicSharedMemorySize, K1_SMEM);

    k1_conv<<<dim3(4, NG), 256, K1_SMEM>>>(x, w3, b3);
    k345<<<NG, 512>>>(x, w1, b1, wh, bh, ww, bw, gamma, beta, out);
}